// round 8
// baseline (speedup 1.0000x reference)
#include <cuda_runtime.h>
#include <cuda_bf16.h>
#include <math.h>

// ---------------- problem constants ----------------
#define S_LEN    4096
#define DMODEL   1024
#define N_HEADS  16
#define HEAD_DIM 64
#define NX (S_LEN * DMODEL)
#define NW (DMODEL * DMODEL)

// ---------------- scratch (no allocations allowed) ----------------
// int8 quantized planes: value = scale_row * (128*h + l)
__device__ signed char g_x8h[NX], g_x8l[NX];
__device__ float g_xs[S_LEN];
__device__ signed char g_Wq8h[NW], g_Wq8l[NW];  __device__ float g_Wqs[DMODEL];
__device__ signed char g_Wk8h[NW], g_Wk8l[NW];  __device__ float g_Wks[DMODEL];
__device__ signed char g_Wv8h[NW], g_Wv8l[NW];  __device__ float g_Wvs[DMODEL];
__device__ signed char g_Wo8h[NW], g_Wo8l[NW];  __device__ float g_Wos[DMODEL];
__device__ signed char g_c8h[NX], g_c8l[NX];
__device__ float g_cs[S_LEN];
__device__ float g_ctx[NX];
// bf16 hi/lo planes for attention
__device__ unsigned short g_qh[NX], g_ql[NX];
__device__ unsigned short g_kh[NX], g_kl[NX];
__device__ unsigned short g_vh[NX], g_vl[NX];

// ---------------- small helpers ----------------
__device__ __forceinline__ unsigned smem_u32(const void* p) {
    unsigned a;
    asm("{ .reg .u64 t; cvta.to.shared.u64 t, %1; cvt.u32.u64 %0, t; }" : "=r"(a) : "l"(p));
    return a;
}
__device__ __forceinline__ void cp16(unsigned dst, const void* src) {
    asm volatile("cp.async.cg.shared.global [%0], [%1], 16;" :: "r"(dst), "l"(src));
}
__device__ __forceinline__ void ldm_x4(unsigned* r, unsigned addr) {
    asm volatile("ldmatrix.sync.aligned.m8n8.x4.shared.b16 {%0,%1,%2,%3}, [%4];"
                 : "=r"(r[0]), "=r"(r[1]), "=r"(r[2]), "=r"(r[3]) : "r"(addr));
}
__device__ __forceinline__ void ldm_x4t(unsigned* r, unsigned addr) {
    asm volatile("ldmatrix.sync.aligned.m8n8.x4.trans.shared.b16 {%0,%1,%2,%3}, [%4];"
                 : "=r"(r[0]), "=r"(r[1]), "=r"(r[2]), "=r"(r[3]) : "r"(addr));
}
__device__ __forceinline__ void mma16816(float* d, const unsigned* a, const unsigned* b) {
    asm volatile(
        "mma.sync.aligned.m16n8k16.row.col.f32.bf16.bf16.f32 "
        "{%0,%1,%2,%3}, {%4,%5,%6,%7}, {%8,%9}, {%0,%1,%2,%3};"
        : "+f"(d[0]), "+f"(d[1]), "+f"(d[2]), "+f"(d[3])
        : "r"(a[0]), "r"(a[1]), "r"(a[2]), "r"(a[3]), "r"(b[0]), "r"(b[1]));
}
__device__ __forceinline__ void imma(int* d, const unsigned* a, const unsigned* b) {
    asm volatile(
        "mma.sync.aligned.m16n8k32.row.col.s32.s8.s8.s32 "
        "{%0,%1,%2,%3}, {%4,%5,%6,%7}, {%8,%9}, {%0,%1,%2,%3};"
        : "+r"(d[0]), "+r"(d[1]), "+r"(d[2]), "+r"(d[3])
        : "r"(a[0]), "r"(a[1]), "r"(a[2]), "r"(a[3]), "r"(b[0]), "r"(b[1]));
}
__device__ __forceinline__ unsigned packbf(float lo, float hi) {
    unsigned r;
    asm("cvt.rn.bf16x2.f32 %0, %1, %2;" : "=r"(r) : "f"(hi), "f"(lo));
    return r;
}
__device__ __forceinline__ float bflo_f(unsigned u) { return __uint_as_float(u << 16); }
__device__ __forceinline__ float bfhi_f(unsigned u) { return __uint_as_float(u & 0xffff0000u); }
__device__ __forceinline__ float ex2(float x) {
    float y; asm("ex2.approx.ftz.f32 %0, %1;" : "=f"(y) : "f"(x)); return y;
}
__device__ __forceinline__ float rcp(float x) {
    float y; asm("rcp.approx.ftz.f32 %0, %1;" : "=f"(y) : "f"(x)); return y;
}

// ---------------- per-row int8 2-plane quantization ----------------
// x ~= s*(128*h + l), s = rowmax/16256, |h|<=127, |l|<=64.
__global__ __launch_bounds__(256)
void quant_rows(const float* __restrict__ in, signed char* __restrict__ h8,
                signed char* __restrict__ l8, float* __restrict__ sc)
{
    __shared__ float red[8];
    const int row = blockIdx.x, t = threadIdx.x;
    const float* rp = in + (size_t)row * DMODEL;
    float4 v = *(const float4*)(rp + t * 4);
    float m = fmaxf(fmaxf(fabsf(v.x), fabsf(v.y)), fmaxf(fabsf(v.z), fabsf(v.w)));
#pragma unroll
    for (int o = 16; o > 0; o >>= 1)
        m = fmaxf(m, __shfl_xor_sync(0xffffffffu, m, o));
    if ((t & 31) == 0) red[t >> 5] = m;
    __syncthreads();
    float bmax = red[0];
#pragma unroll
    for (int i = 1; i < 8; i++) bmax = fmaxf(bmax, red[i]);
    bmax = fmaxf(bmax, 1e-20f);
    const float s = bmax * (1.0f / 16256.0f);
    const float inv = 16256.0f / bmax;           // 1/s
    const float inv128 = inv * 0.0078125f;       // 1/(128 s)
    const float n128s = -128.0f * s;

    float xs[4] = {v.x, v.y, v.z, v.w};
    int hq[4], lq[4];
#pragma unroll
    for (int i = 0; i < 4; i++) {
        float hf = rintf(xs[i] * inv128);
        float r  = fmaf(hf, n128s, xs[i]);
        float lf = rintf(r * inv);
        hq[i] = (int)hf; lq[i] = (int)lf;
    }
    unsigned hp = (hq[0] & 255) | ((hq[1] & 255) << 8) | ((hq[2] & 255) << 16) | ((unsigned)(hq[3] & 255) << 24);
    unsigned lp = (lq[0] & 255) | ((lq[1] & 255) << 8) | ((lq[2] & 255) << 16) | ((unsigned)(lq[3] & 255) << 24);
    *(unsigned*)(h8 + (size_t)row * DMODEL + t * 4) = hp;
    *(unsigned*)(l8 + (size_t)row * DMODEL + t * 4) = lp;
    if (t == 0) sc[row] = s;
}

// ---------------- int8 4-term GEMM ----------------
// C[m,n] = sa[m]*sb[n]*(16384*hh + 128*(hl+lh) + ll) + bias[n]
// CTA tile 128x64, BK=64 int8, 8 warps (2m x 4n), warp tile 64x16, 2-stage cp.async, 2 CTAs/SM.
#define IROWB  80
#define I_AH   0
#define I_AL   (128 * IROWB)             // 10240
#define I_BH   (2 * 128 * IROWB)         // 20480
#define I_BL   (I_BH + 64 * IROWB)       // 25600
#define ISTAGE (I_BL + 64 * IROWB)       // 30720
#define IGSMEM (2 * ISTAGE)              // 61440
#define INCH   16                        // 1024/64

__device__ __forceinline__
void gemm_i8_body(char* smem,
                  const signed char* __restrict__ Ah, const signed char* __restrict__ Al,
                  const float* __restrict__ As,
                  const signed char* __restrict__ Bh, const signed char* __restrict__ Bl,
                  const float* __restrict__ Bs,
                  const float* __restrict__ bias, int bm, int bn,
                  int mode, float* __restrict__ C,
                  unsigned short* __restrict__ Ch, unsigned short* __restrict__ Cl)
{
    const int t = threadIdx.x, lane = t & 31, wid = t >> 5;
    const int wm = wid >> 2, wn = wid & 3;

    int acc0[4][2][4], acc1[4][2][4], acc2[4][2][4];
#pragma unroll
    for (int mt = 0; mt < 4; mt++)
#pragma unroll
        for (int nt = 0; nt < 2; nt++)
#pragma unroll
            for (int r = 0; r < 4; r++) { acc0[mt][nt][r] = 0; acc1[mt][nt][r] = 0; acc2[mt][nt][r] = 0; }

    const int ra = t >> 2, sg = t & 3;

#define ISSUE(cc)                                                                     \
    {                                                                                 \
        char* sb = smem + ((cc) & 1) * ISTAGE;                                        \
        const int gk = (cc) * 64 + sg * 16;                                           \
        cp16(smem_u32(sb + I_AH + ra * IROWB + sg * 16),                              \
             Ah + (size_t)(bm + ra) * DMODEL + gk);                                   \
        cp16(smem_u32(sb + I_AH + (ra + 64) * IROWB + sg * 16),                       \
             Ah + (size_t)(bm + ra + 64) * DMODEL + gk);                              \
        cp16(smem_u32(sb + I_AL + ra * IROWB + sg * 16),                              \
             Al + (size_t)(bm + ra) * DMODEL + gk);                                   \
        cp16(smem_u32(sb + I_AL + (ra + 64) * IROWB + sg * 16),                       \
             Al + (size_t)(bm + ra + 64) * DMODEL + gk);                              \
        cp16(smem_u32(sb + I_BH + ra * IROWB + sg * 16),                              \
             Bh + (size_t)(bn + ra) * DMODEL + gk);                                   \
        cp16(smem_u32(sb + I_BL + ra * IROWB + sg * 16),                              \
             Bl + (size_t)(bn + ra) * DMODEL + gk);                                   \
        asm volatile("cp.async.commit_group;" ::: "memory");                          \
    }

    ISSUE(0); ISSUE(1);

    const int a_row = wm * 64 + (lane & 15);
    const unsigned a_coff = (lane >> 4) << 4;
    const int b_row = wn * 16 + (lane & 7) + ((lane >> 4) << 3);
    const unsigned b_coff = ((lane >> 3) & 1) << 4;

    for (int c = 0; c < INCH; c++) {
        if (c + 1 < INCH) {
            asm volatile("cp.async.wait_group 1;" ::: "memory");
        } else {
            asm volatile("cp.async.wait_group 0;" ::: "memory");
        }
        __syncthreads();

        char* sb = smem + (c & 1) * ISTAGE;
        const unsigned sAH = smem_u32(sb) + I_AH;
        const unsigned sAL = smem_u32(sb) + I_AL;
        const unsigned sBH = smem_u32(sb) + I_BH;
        const unsigned sBL = smem_u32(sb) + I_BL;

#pragma unroll
        for (int ks = 0; ks < 2; ks++) {
            const unsigned ka = ks * 32;
            unsigned bh4[4], bl4[4];
            unsigned boff = (unsigned)(b_row * IROWB) + ka + b_coff;
            ldm_x4(bh4, sBH + boff);
            ldm_x4(bl4, sBL + boff);
#pragma unroll
            for (int mt = 0; mt < 4; mt++) {
                unsigned ah[4], al[4];
                unsigned aoff = (unsigned)((a_row + mt * 16) * IROWB) + ka + a_coff;
                ldm_x4(ah, sAH + aoff);
                ldm_x4(al, sAL + aoff);
#pragma unroll
                for (int nt = 0; nt < 2; nt++) {
                    imma(acc0[mt][nt], ah, bh4 + nt * 2);
                    imma(acc1[mt][nt], ah, bl4 + nt * 2);
                    imma(acc1[mt][nt], al, bh4 + nt * 2);
                    imma(acc2[mt][nt], al, bl4 + nt * 2);
                }
            }
        }
        __syncthreads();
        if (c + 2 < INCH) ISSUE(c + 2);
    }
#undef ISSUE

    // ---- epilogue ----
    const int er = lane >> 2, ec = (lane & 3) * 2;
#pragma unroll
    for (int mt = 0; mt < 4; mt++) {
        const int row0 = bm + wm * 64 + mt * 16 + er;
        const float sa0 = As[row0], sa1 = As[row0 + 8];
#pragma unroll
        for (int nt = 0; nt < 2; nt++) {
            const int col = bn + wn * 16 + nt * 8 + ec;
            const float sb0 = Bs[col], sb1 = Bs[col + 1];
            const float b0 = bias[col], b1 = bias[col + 1];
            float v0 = fmaf(16384.f * (float)acc0[mt][nt][0] + 128.f * (float)acc1[mt][nt][0]
                            + (float)acc2[mt][nt][0], sa0 * sb0, b0);
            float v1 = fmaf(16384.f * (float)acc0[mt][nt][1] + 128.f * (float)acc1[mt][nt][1]
                            + (float)acc2[mt][nt][1], sa0 * sb1, b1);
            float v2 = fmaf(16384.f * (float)acc0[mt][nt][2] + 128.f * (float)acc1[mt][nt][2]
                            + (float)acc2[mt][nt][2], sa1 * sb0, b0);
            float v3 = fmaf(16384.f * (float)acc0[mt][nt][3] + 128.f * (float)acc1[mt][nt][3]
                            + (float)acc2[mt][nt][3], sa1 * sb1, b1);
            if (mode == 0) {
                *(float2*)&C[(size_t)row0 * DMODEL + col] = make_float2(v0, v1);
                *(float2*)&C[(size_t)(row0 + 8) * DMODEL + col] = make_float2(v2, v3);
            } else {
                unsigned hp0 = packbf(v0, v1);
                unsigned lp0 = packbf(v0 - bflo_f(hp0), v1 - bfhi_f(hp0));
                unsigned hp1 = packbf(v2, v3);
                unsigned lp1 = packbf(v2 - bflo_f(hp1), v3 - bfhi_f(hp1));
                *(unsigned*)&Ch[(size_t)row0 * DMODEL + col] = hp0;
                *(unsigned*)&Cl[(size_t)row0 * DMODEL + col] = lp0;
                *(unsigned*)&Ch[(size_t)(row0 + 8) * DMODEL + col] = hp1;
                *(unsigned*)&Cl[(size_t)(row0 + 8) * DMODEL + col] = lp1;
            }
        }
    }
}

// ---- fused QKV projection: grid (48, 32); blockIdx.x>>4 selects Q/K/V ----
__global__ __launch_bounds__(256, 2)
void gemm_qkv(const float* __restrict__ bq, const float* __restrict__ bk,
              const float* __restrict__ bv)
{
    extern __shared__ char smem[];
    const int which = blockIdx.x >> 4;
    const int bn = (blockIdx.x & 15) * 64;
    const int bm = blockIdx.y * 128;
    const signed char* Bh = (which == 0) ? g_Wq8h : (which == 1) ? g_Wk8h : g_Wv8h;
    const signed char* Bl = (which == 0) ? g_Wq8l : (which == 1) ? g_Wk8l : g_Wv8l;
    const float* Bs = (which == 0) ? g_Wqs : (which == 1) ? g_Wks : g_Wvs;
    const float* bias = (which == 0) ? bq : (which == 1) ? bk : bv;
    unsigned short* Ch = (which == 0) ? g_qh : (which == 1) ? g_kh : g_vh;
    unsigned short* Cl = (which == 0) ? g_ql : (which == 1) ? g_kl : g_vl;
    gemm_i8_body(smem, g_x8h, g_x8l, g_xs, Bh, Bl, Bs, bias, bm, bn, 1, nullptr, Ch, Cl);
}

// ---- output projection: ctx(int8) @ Wo^T + bo -> fp32 out ----
__global__ __launch_bounds__(256, 2)
void gemm_out(const float* __restrict__ bo, float* __restrict__ out)
{
    extern __shared__ char smem[];
    gemm_i8_body(smem, g_c8h, g_c8l, g_cs, g_Wo8h, g_Wo8l, g_Wos, bo,
                 blockIdx.y * 128, blockIdx.x * 64, 0, out, nullptr, nullptr);
}

// ---------------- tensorized sliding-window attention (bf16x3, from R6) ----------------
#define AT_Q   64
#define AT_K   192
#define AROWB  144
#define A_SQH  0
#define A_SQL  (64 * AROWB)
#define A_SKH  (2 * 64 * AROWB)
#define A_SKL  (A_SKH + AT_K * AROWB)
#define A_SVH  (A_SKL + AT_K * AROWB)
#define A_SVL  (A_SVH + AT_K * AROWB)
#define A_SMEM (A_SVL + AT_K * AROWB)       // 129024

__global__ __launch_bounds__(128)
void attn_mma()
{
    extern __shared__ char smem[];
    const unsigned sb = smem_u32(smem);
    const int t = threadIdx.x, lane = t & 31, w = t >> 5;
    const int h = blockIdx.y;
    const int q0 = blockIdx.x * AT_Q;
    const int j0 = q0 - 64;
    const int col = h * HEAD_DIM;

#pragma unroll
    for (int i = 0; i < 4; i++) {
        int idx = t + i * 128;
        int r = idx >> 3, sg = idx & 7;
        size_t go = (size_t)(q0 + r) * DMODEL + col + sg * 8;
        *(uint4*)(smem + A_SQH + r * AROWB + sg * 16) = *(const uint4*)(g_qh + go);
        *(uint4*)(smem + A_SQL + r * AROWB + sg * 16) = *(const uint4*)(g_ql + go);
    }
#pragma unroll
    for (int i = 0; i < 12; i++) {
        int idx = t + i * 128;
        int r = idx >> 3, sg = idx & 7;
        int j = j0 + r;
        uint4 kh = make_uint4(0,0,0,0), kl = kh, vh = kh, vl = kh;
        if ((unsigned)j < (unsigned)S_LEN) {
            size_t go = (size_t)j * DMODEL + col + sg * 8;
            kh = *(const uint4*)(g_kh + go);
            kl = *(const uint4*)(g_kl + go);
            vh = *(const uint4*)(g_vh + go);
            vl = *(const uint4*)(g_vl + go);
        }
        unsigned so = r * AROWB + sg * 16;
        *(uint4*)(smem + A_SKH + so) = kh;
        *(uint4*)(smem + A_SKL + so) = kl;
        *(uint4*)(smem + A_SVH + so) = vh;
        *(uint4*)(smem + A_SVL + so) = vl;
    }
    __syncthreads();

    float sc[24][4];
#pragma unroll
    for (int nt = 0; nt < 24; nt++)
#pragma unroll
        for (int r = 0; r < 4; r++) sc[nt][r] = 0.f;

    const unsigned a_base = (unsigned)((w * 16 + (lane & 15)) * AROWB) + ((lane >> 4) << 4);
    const int b_lrow = (lane & 7) + ((lane >> 4) << 3);
    const unsigned b_coff = ((lane >> 3) & 1) << 4;

#pragma unroll
    for (int kc = 0; kc < 4; kc++) {
        unsigned ah[4], al[4];
        ldm_x4(ah, sb + A_SQH + a_base + kc * 32);
        ldm_x4(al, sb + A_SQL + a_base + kc * 32);
#pragma unroll
        for (int pr = 0; pr < 12; pr++) {
            unsigned bh[4], bl[4];
            unsigned off = (unsigned)((pr * 16 + b_lrow) * AROWB) + kc * 32 + b_coff;
            ldm_x4(bh, sb + A_SKH + off);
            ldm_x4(bl, sb + A_SKL + off);
#pragma unroll
            for (int half = 0; half < 2; half++) {
                const int nt = pr * 2 + half;
                mma16816(sc[nt], ah, &bh[half * 2]);
                mma16816(sc[nt], ah, &bl[half * 2]);
                mma16816(sc[nt], al, &bh[half * 2]);
            }
        }
    }

    const int er = lane >> 2, ec = (lane & 3) * 2;
    const int qa = w * 16 + er, qb = qa + 8;
    const float SC = 0.125f * 1.44269504088896f;
    float m0 = -1e30f, m1 = -1e30f;
#pragma unroll
    for (int nt = 0; nt < 24; nt++) {
        int kl = nt * 8 + ec;
        int j  = j0 + kl;
        bool v00 = ((unsigned)(kl     - qa) <= 128u) && ((unsigned)j       < (unsigned)S_LEN);
        bool v01 = ((unsigned)(kl + 1 - qa) <= 128u) && ((unsigned)(j + 1) < (unsigned)S_LEN);
        bool v10 = ((unsigned)(kl     - qb) <= 128u) && ((unsigned)j       < (unsigned)S_LEN);
        bool v11 = ((unsigned)(kl + 1 - qb) <= 128u) && ((unsigned)(j + 1) < (unsigned)S_LEN);
        sc[nt][0] = v00 ? sc[nt][0] * SC : -1e30f;
        sc[nt][1] = v01 ? sc[nt][1] * SC : -1e30f;
        sc[nt][2] = v10 ? sc[nt][2] * SC : -1e30f;
        sc[nt][3] = v11 ? sc[nt][3] * SC : -1e30f;
        m0 = fmaxf(m0, fmaxf(sc[nt][0], sc[nt][1]));
        m1 = fmaxf(m1, fmaxf(sc[nt][2], sc[nt][3]));
    }
    m0 = fmaxf(m0, __shfl_xor_sync(0xffffffffu, m0, 1));
    m0 = fmaxf(m0, __shfl_xor_sync(0xffffffffu, m0, 2));
    m1 = fmaxf(m1, __shfl_xor_sync(0xffffffffu, m1, 1));
    m1 = fmaxf(m1, __shfl_xor_sync(0xffffffffu, m1, 2));

    float s0 = 0.f, s1 = 0.f;
#pragma unroll
    for (int nt = 0; nt < 24; nt++) {
        sc[nt][0] = ex2(sc[nt][0] - m0);
        sc[nt][1] = ex2(sc[nt][1] - m0);
        sc[nt][2] = ex2(sc[nt][2] - m1);
        sc[nt][3] = ex2(sc[nt][3] - m1);
        s0 += sc[nt][0] + sc[nt][1];
        s1 += sc[nt][2] + sc[nt][3];
    }
    s0 += __shfl_xor_sync(0xffffffffu, s0, 1);
    s0 += __shfl_xor_sync(0xffffffffu, s0, 2);
    s1 += __shfl_xor_sync(0xffffffffu, s1, 1);
    s1 += __shfl_xor_sync(0xffffffffu, s1, 2);
    const float inv0 = rcp(s0), inv1 = rcp(s1);

    float oa[8][4];
#pragma unroll
    for (int nt = 0; nt < 8; nt++)
#pragma unroll
        for (int r = 0; r < 4; r++) oa[nt][r] = 0.f;

#pragma unroll
    for (int kc = 0; kc < 12; kc++) {
        unsigned ph[4], pl[4];
        ph[0] = packbf(sc[2 * kc][0],     sc[2 * kc][1]);
        ph[1] = packbf(sc[2 * kc][2],     sc[2 * kc][3]);
        ph[2] = packbf(sc[2 * kc + 1][0], sc[2 * kc + 1][1]);
        ph[3] = packbf(sc[2 * kc + 1][2], sc[2 * kc + 1][3]);
        pl[0] = packbf(sc[2 * kc][0]     - bflo_f(ph[0]), sc[2 * kc][1]     - bfhi_f(ph[0]));
        pl[1] = packbf(sc[2 * kc][2]     - bflo_f(ph[1]), sc[2 * kc][3]     - bfhi_f(ph[1]));
        pl[2] = packbf(sc[2 * kc + 1][0] - bflo_f(ph[2]), sc[2 * kc + 1][1] - bfhi_f(ph[2]));
        pl[3] = packbf(sc[2 * kc + 1][2] - bflo_f(ph[3]), sc[2 * kc + 1][3] - bfhi_f(ph[3]));
#pragma unroll
        for (int dt = 0; dt < 4; dt++) {
            unsigned vh[4], vl[4];
            unsigned voff = (unsigned)((kc * 16 + (lane & 15)) * AROWB) + dt * 32 + ((lane >> 4) << 4);
            ldm_x4t(vh, sb + A_SVH + voff);
            ldm_x4t(vl, sb + A_SVL + voff);
            mma16816(oa[2 * dt],     ph, &vh[0]);
            mma16816(oa[2 * dt],     ph, &vl[0]);
            mma16816(oa[2 * dt],     pl, &vh[0]);
            mma16816(oa[2 * dt + 1], ph, &vh[2]);
            mma16816(oa[2 * dt + 1], ph, &vl[2]);
            mma16816(oa[2 * dt + 1], pl, &vh[2]);
        }
    }

    // ---- normalize + write ctx as fp32 (quantized afterwards) ----
    const int row0 = q0 + w * 16 + er;
#pragma unroll
    for (int nt = 0; nt < 8; nt++) {
        const int oc = col + nt * 8 + ec;
        float v0 = oa[nt][0] * inv0, v1 = oa[nt][1] * inv0;
        float v2 = oa[nt][2] * inv1, v3 = oa[nt][3] * inv1;
        *(float2*)&g_ctx[(size_t)row0 * DMODEL + oc] = make_float2(v0, v1);
        *(float2*)&g_ctx[(size_t)(row0 + 8) * DMODEL + oc] = make_float2(v2, v3);
    }
}

// ---------------- launch ----------------
extern "C" void kernel_launch(void* const* d_in, const int* in_sizes, int n_in,
                              void* d_out, int out_size)
{
    const float* x  = (const float*)d_in[0];
    const float* Wq = (const float*)d_in[1];
    const float* bq = (const float*)d_in[2];
    const float* Wk = (const float*)d_in[3];
    const float* bk = (const float*)d_in[4];
    const float* Wv = (const float*)d_in[5];
    const float* bv = (const float*)d_in[6];
    const float* Wo = (const float*)d_in[7];
    const float* bo = (const float*)d_in[8];
    float* out = (float*)d_out;

    signed char *x8h, *x8l, *c8h, *c8l;
    signed char *wq8h, *wq8l, *wk8h, *wk8l, *wv8h, *wv8l, *wo8h, *wo8l;
    float *xs, *cs, *wqs, *wks, *wvs, *wos, *ctx;
    cudaGetSymbolAddress((void**)&x8h, g_x8h);   cudaGetSymbolAddress((void**)&x8l, g_x8l);
    cudaGetSymbolAddress((void**)&xs,  g_xs);
    cudaGetSymbolAddress((void**)&wq8h, g_Wq8h); cudaGetSymbolAddress((void**)&wq8l, g_Wq8l);
    cudaGetSymbolAddress((void**)&wqs, g_Wqs);
    cudaGetSymbolAddress((void**)&wk8h, g_Wk8h); cudaGetSymbolAddress((void**)&wk8l, g_Wk8l);
    cudaGetSymbolAddress((void**)&wks, g_Wks);
    cudaGetSymbolAddress((void**)&wv8h, g_Wv8h); cudaGetSymbolAddress((void**)&wv8l, g_Wv8l);
    cudaGetSymbolAddress((void**)&wvs, g_Wvs);
    cudaGetSymbolAddress((void**)&wo8h, g_Wo8h); cudaGetSymbolAddress((void**)&wo8l, g_Wo8l);
    cudaGetSymbolAddress((void**)&wos, g_Wos);
    cudaGetSymbolAddress((void**)&c8h, g_c8h);   cudaGetSymbolAddress((void**)&c8l, g_c8l);
    cudaGetSymbolAddress((void**)&cs,  g_cs);
    cudaGetSymbolAddress((void**)&ctx, g_ctx);

    cudaFuncSetAttribute(gemm_qkv, cudaFuncAttributeMaxDynamicSharedMemorySize, IGSMEM);
    cudaFuncSetAttribute(gemm_out, cudaFuncAttributeMaxDynamicSharedMemorySize, IGSMEM);
    cudaFuncSetAttribute(attn_mma, cudaFuncAttributeMaxDynamicSharedMemorySize, A_SMEM);

    quant_rows<<<S_LEN,  256>>>(x,  x8h,  x8l,  xs);
    quant_rows<<<DMODEL, 256>>>(Wq, wq8h, wq8l, wqs);
    quant_rows<<<DMODEL, 256>>>(Wk, wk8h, wk8l, wks);
    quant_rows<<<DMODEL, 256>>>(Wv, wv8h, wv8l, wvs);
    quant_rows<<<DMODEL, 256>>>(Wo, wo8h, wo8l, wos);

    dim3 gq(48, 32);                      // fused Q,K,V (16 n-tiles each)
    gemm_qkv<<<gq, 256, IGSMEM>>>(bq, bk, bv);

    dim3 ga(S_LEN / AT_Q, N_HEADS);       // (64, 16)
    attn_mma<<<ga, 128, A_SMEM>>>();

    quant_rows<<<S_LEN, 256>>>(ctx, c8h, c8l, cs);

    dim3 go(16, 32);
    gemm_out<<<go, 256, IGSMEM>>>(bo, out);
}

// round 9
// speedup vs baseline: 6.2600x; 6.2600x over previous
#include <cuda_runtime.h>
#include <cuda_fp16.h>
#include <math.h>

// ---------------- problem constants ----------------
#define S_LEN    4096
#define DMODEL   1024
#define N_HEADS  16
#define HEAD_DIM 64
#define NX (S_LEN * DMODEL)
#define NW (DMODEL * DMODEL)

// ---------------- scratch: single-plane fp16 ----------------
__device__ unsigned short g_x16[NX];
__device__ unsigned short g_q16[NX];
__device__ unsigned short g_k16[NX];
__device__ unsigned short g_v16[NX];
__device__ unsigned short g_c16[NX];
__device__ unsigned short g_Wq16[NW];
__device__ unsigned short g_Wk16[NW];
__device__ unsigned short g_Wv16[NW];
__device__ unsigned short g_Wo16[NW];

// ---------------- small helpers ----------------
__device__ __forceinline__ unsigned smem_u32(const void* p) {
    unsigned a;
    asm("{ .reg .u64 t; cvta.to.shared.u64 t, %1; cvt.u32.u64 %0, t; }" : "=r"(a) : "l"(p));
    return a;
}
__device__ __forceinline__ void cp16(unsigned dst, const void* src) {
    asm volatile("cp.async.cg.shared.global [%0], [%1], 16;" :: "r"(dst), "l"(src));
}
__device__ __forceinline__ void ldm_x4(unsigned* r, unsigned addr) {
    asm volatile("ldmatrix.sync.aligned.m8n8.x4.shared.b16 {%0,%1,%2,%3}, [%4];"
                 : "=r"(r[0]), "=r"(r[1]), "=r"(r[2]), "=r"(r[3]) : "r"(addr));
}
__device__ __forceinline__ void ldm_x4t(unsigned* r, unsigned addr) {
    asm volatile("ldmatrix.sync.aligned.m8n8.x4.trans.shared.b16 {%0,%1,%2,%3}, [%4];"
                 : "=r"(r[0]), "=r"(r[1]), "=r"(r[2]), "=r"(r[3]) : "r"(addr));
}
__device__ __forceinline__ void mma_f16(float* d, const unsigned* a, const unsigned* b) {
    asm volatile(
        "mma.sync.aligned.m16n8k16.row.col.f32.f16.f16.f32 "
        "{%0,%1,%2,%3}, {%4,%5,%6,%7}, {%8,%9}, {%0,%1,%2,%3};"
        : "+f"(d[0]), "+f"(d[1]), "+f"(d[2]), "+f"(d[3])
        : "r"(a[0]), "r"(a[1]), "r"(a[2]), "r"(a[3]), "r"(b[0]), "r"(b[1]));
}
__device__ __forceinline__ unsigned packf16(float lo, float hi) {
    unsigned r;
    asm("cvt.rn.f16x2.f32 %0, %1, %2;" : "=r"(r) : "f"(hi), "f"(lo));
    return r;
}
__device__ __forceinline__ float ex2(float x) {
    float y; asm("ex2.approx.ftz.f32 %0, %1;" : "=f"(y) : "f"(x)); return y;
}
__device__ __forceinline__ float rcp(float x) {
    float y; asm("rcp.approx.ftz.f32 %0, %1;" : "=f"(y) : "f"(x)); return y;
}

// ---------------- convert fp32 -> fp16 ----------------
__global__ __launch_bounds__(256)
void to_f16(const float* __restrict__ in, unsigned short* __restrict__ out)
{
    int i = (blockIdx.x * 256 + threadIdx.x) * 4;
    float4 a = *(const float4*)(in + i);
    *(uint2*)(out + i) = make_uint2(packf16(a.x, a.y), packf16(a.z, a.w));
}

// all four weight matrices in one launch (grid 4096, 1024 blocks each)
__global__ __launch_bounds__(256)
void to_f16_w(const float* __restrict__ wq, const float* __restrict__ wk,
              const float* __restrict__ wv, const float* __restrict__ wo)
{
    const int which = blockIdx.x >> 10;
    const int bi = blockIdx.x & 1023;
    const float* src = (which == 0) ? wq : (which == 1) ? wk : (which == 2) ? wv : wo;
    unsigned short* dst = (which == 0) ? g_Wq16 : (which == 1) ? g_Wk16
                        : (which == 2) ? g_Wv16 : g_Wo16;
    int i = (bi * 256 + threadIdx.x) * 4;
    float4 a = *(const float4*)(src + i);
    *(uint2*)(dst + i) = make_uint2(packf16(a.x, a.y), packf16(a.z, a.w));
}

// ---------------- fp16 GEMM: C = A @ B^T + bias ----------------
// 128x128 tile, BK=32, 8 warps (2x4), warp tile 64x32, 2-stage cp.async.
#define ROWB   80
#define PLANE  (128 * ROWB)              // 10240
#define STAGE  (2 * PLANE)               // 20480 (A + B)
#define GSMEM  (2 * STAGE)               // 40960
#define NCHUNK 32

__device__ __forceinline__
void gemm_body(char* smem,
               const unsigned short* __restrict__ A, const unsigned short* __restrict__ B,
               const float* __restrict__ bias, int bm, int bn,
               int mode, float* __restrict__ C, unsigned short* __restrict__ Ch)
{
    const int t = threadIdx.x, lane = t & 31, wid = t >> 5;
    const int wm = wid >> 2, wn = wid & 3;

    float acc[4][4][4];
#pragma unroll
    for (int mt = 0; mt < 4; mt++)
#pragma unroll
        for (int nt = 0; nt < 4; nt++)
#pragma unroll
            for (int r = 0; r < 4; r++) acc[mt][nt][r] = 0.f;

    const int r0 = t >> 2, s0 = t & 3;
    const int r1 = r0 + 64;

#define ISSUE(cc)                                                                 \
    {                                                                             \
        char* sb = smem + ((cc) & 1) * STAGE;                                     \
        const int gk = (cc) * 32 + s0 * 8;                                        \
        const unsigned short* ga = A + (size_t)(bm + r0) * DMODEL + gk;           \
        const unsigned short* gb = B + (size_t)(bn + r0) * DMODEL + gk;           \
        unsigned da = smem_u32(sb + s0 * 16);                                     \
        unsigned db = smem_u32(sb + PLANE + s0 * 16);                             \
        cp16(da + r0 * ROWB, ga);                                                 \
        cp16(da + r1 * ROWB, ga + (size_t)64 * DMODEL);                           \
        cp16(db + r0 * ROWB, gb);                                                 \
        cp16(db + r1 * ROWB, gb + (size_t)64 * DMODEL);                           \
        asm volatile("cp.async.commit_group;" ::: "memory");                      \
    }

    ISSUE(0); ISSUE(1);

    const int a_row = wm * 64 + (lane & 15);
    const unsigned a_coff = (lane >> 4) * 16;
    const int b_row = wn * 32 + (lane & 7) + ((lane >> 4) << 3);
    const unsigned b_coff = ((lane >> 3) & 1) * 16;

    for (int c = 0; c < NCHUNK; c++) {
        if (c + 1 < NCHUNK) {
            asm volatile("cp.async.wait_group 1;" ::: "memory");
        } else {
            asm volatile("cp.async.wait_group 0;" ::: "memory");
        }
        __syncthreads();

        char* sb = smem + (c & 1) * STAGE;
        const unsigned sA = smem_u32(sb);
        const unsigned sB = sA + PLANE;

#pragma unroll
        for (int ks = 0; ks < 2; ks++) {
            const unsigned ka = ks * 32;
            unsigned bfr[2][4];
#pragma unroll
            for (int pr = 0; pr < 2; pr++)
                ldm_x4(bfr[pr], sB + (unsigned)((b_row + pr * 16) * ROWB) + ka + b_coff);
#pragma unroll
            for (int mt = 0; mt < 4; mt++) {
                unsigned afr[4];
                ldm_x4(afr, sA + (unsigned)((a_row + mt * 16) * ROWB) + ka + a_coff);
#pragma unroll
                for (int pr = 0; pr < 2; pr++)
#pragma unroll
                    for (int half = 0; half < 2; half++)
                        mma_f16(acc[mt][pr * 2 + half], afr, &bfr[pr][half * 2]);
            }
        }
        __syncthreads();
        if (c + 2 < NCHUNK) ISSUE(c + 2);
    }
#undef ISSUE

    // ---- epilogue ----
    const int er = lane >> 2, ec = (lane & 3) * 2;
#pragma unroll
    for (int mt = 0; mt < 4; mt++) {
        const int row = bm + wm * 64 + mt * 16 + er;
#pragma unroll
        for (int nt = 0; nt < 4; nt++) {
            const int col = bn + wn * 32 + nt * 8 + ec;
            const float b0 = bias[col], b1 = bias[col + 1];
            float v0 = acc[mt][nt][0] + b0, v1 = acc[mt][nt][1] + b1;
            float v2 = acc[mt][nt][2] + b0, v3 = acc[mt][nt][3] + b1;
            if (mode == 0) {
                *(float2*)&C[(size_t)row * DMODEL + col] = make_float2(v0, v1);
                *(float2*)&C[(size_t)(row + 8) * DMODEL + col] = make_float2(v2, v3);
            } else {
                *(unsigned*)&Ch[(size_t)row * DMODEL + col] = packf16(v0, v1);
                *(unsigned*)&Ch[(size_t)(row + 8) * DMODEL + col] = packf16(v2, v3);
            }
        }
    }
}

// ---- fused QKV projection: grid (24, 32); blockIdx.x/8 selects Q/K/V ----
__global__ __launch_bounds__(256, 2)
void gemm_qkv(const float* __restrict__ bq, const float* __restrict__ bk,
              const float* __restrict__ bv)
{
    extern __shared__ char smem[];
    const int which = blockIdx.x >> 3;
    const int bn = (blockIdx.x & 7) * 128;
    const int bm = blockIdx.y * 128;
    const unsigned short* B = (which == 0) ? g_Wq16 : (which == 1) ? g_Wk16 : g_Wv16;
    const float* bias = (which == 0) ? bq : (which == 1) ? bk : bv;
    unsigned short* Ch = (which == 0) ? g_q16 : (which == 1) ? g_k16 : g_v16;
    gemm_body(smem, g_x16, B, bias, bm, bn, 1, nullptr, Ch);
}

// ---- output projection: ctx(f16) @ Wo^T + bo -> fp32 out ----
__global__ __launch_bounds__(256, 2)
void gemm_out(const float* __restrict__ bo, float* __restrict__ out)
{
    extern __shared__ char smem[];
    gemm_body(smem, g_c16, g_Wo16, bo,
              blockIdx.y * 128, blockIdx.x * 128, 0, out, nullptr);
}

// ---------------- tensorized sliding-window attention (fp16) ----------------
// grid (S/64, H), 128 threads (4 warps). Each warp: 16 query rows x 192 keys.
#define AT_Q   64
#define AT_K   192
#define AROWB  144
#define A_SQ   0
#define A_SK   (64 * AROWB)                 // 9216
#define A_SV   (A_SK + AT_K * AROWB)        // 36864
#define A_SMEM (A_SV + AT_K * AROWB)        // 64512 -> 2 CTAs/SM

__global__ __launch_bounds__(128)
void attn_mma()
{
    extern __shared__ char smem[];
    const unsigned sb = smem_u32(smem);
    const int t = threadIdx.x, lane = t & 31, w = t >> 5;
    const int h = blockIdx.y;
    const int q0 = blockIdx.x * AT_Q;
    const int j0 = q0 - 64;
    const int col = h * HEAD_DIM;

    // ---- load Q (64x64) ----
#pragma unroll
    for (int i = 0; i < 4; i++) {
        int idx = t + i * 128;               // 0..511
        int r = idx >> 3, sg = idx & 7;
        *(uint4*)(smem + A_SQ + r * AROWB + sg * 16) =
            *(const uint4*)(g_q16 + (size_t)(q0 + r) * DMODEL + col + sg * 8);
    }
    // ---- load K,V window (192x64), zero-fill out of range ----
#pragma unroll
    for (int i = 0; i < 12; i++) {
        int idx = t + i * 128;               // 0..1535
        int r = idx >> 3, sg = idx & 7;
        int j = j0 + r;
        uint4 kv = make_uint4(0,0,0,0), vv = kv;
        if ((unsigned)j < (unsigned)S_LEN) {
            size_t go = (size_t)j * DMODEL + col + sg * 8;
            kv = *(const uint4*)(g_k16 + go);
            vv = *(const uint4*)(g_v16 + go);
        }
        unsigned so = r * AROWB + sg * 16;
        *(uint4*)(smem + A_SK + so) = kv;
        *(uint4*)(smem + A_SV + so) = vv;
    }
    __syncthreads();

    // ---- S = Q K^T ----
    float sc[24][4];
#pragma unroll
    for (int nt = 0; nt < 24; nt++)
#pragma unroll
        for (int r = 0; r < 4; r++) sc[nt][r] = 0.f;

    const unsigned a_base = (unsigned)((w * 16 + (lane & 15)) * AROWB) + ((lane >> 4) << 4);
    const int b_lrow = (lane & 7) + ((lane >> 4) << 3);
    const unsigned b_coff = ((lane >> 3) & 1) << 4;

#pragma unroll
    for (int kc = 0; kc < 4; kc++) {
        unsigned afr[4];
        ldm_x4(afr, sb + A_SQ + a_base + kc * 32);
#pragma unroll
        for (int pr = 0; pr < 12; pr++) {
            unsigned bfr[4];
            ldm_x4(bfr, sb + A_SK + (unsigned)((pr * 16 + b_lrow) * AROWB) + kc * 32 + b_coff);
            mma_f16(sc[pr * 2],     afr, &bfr[0]);
            mma_f16(sc[pr * 2 + 1], afr, &bfr[2]);
        }
    }

    // ---- mask + softmax ----
    const int er = lane >> 2, ec = (lane & 3) * 2;
    const int qa = w * 16 + er, qb = qa + 8;
    const float SC = 0.125f * 1.44269504088896f;
    float m0 = -1e30f, m1 = -1e30f;
#pragma unroll
    for (int nt = 0; nt < 24; nt++) {
        int kl = nt * 8 + ec;
        int j  = j0 + kl;
        bool v00 = ((unsigned)(kl     - qa) <= 128u) && ((unsigned)j       < (unsigned)S_LEN);
        bool v01 = ((unsigned)(kl + 1 - qa) <= 128u) && ((unsigned)(j + 1) < (unsigned)S_LEN);
        bool v10 = ((unsigned)(kl     - qb) <= 128u) && ((unsigned)j       < (unsigned)S_LEN);
        bool v11 = ((unsigned)(kl + 1 - qb) <= 128u) && ((unsigned)(j + 1) < (unsigned)S_LEN);
        sc[nt][0] = v00 ? sc[nt][0] * SC : -1e30f;
        sc[nt][1] = v01 ? sc[nt][1] * SC : -1e30f;
        sc[nt][2] = v10 ? sc[nt][2] * SC : -1e30f;
        sc[nt][3] = v11 ? sc[nt][3] * SC : -1e30f;
        m0 = fmaxf(m0, fmaxf(sc[nt][0], sc[nt][1]));
        m1 = fmaxf(m1, fmaxf(sc[nt][2], sc[nt][3]));
    }
    m0 = fmaxf(m0, __shfl_xor_sync(0xffffffffu, m0, 1));
    m0 = fmaxf(m0, __shfl_xor_sync(0xffffffffu, m0, 2));
    m1 = fmaxf(m1, __shfl_xor_sync(0xffffffffu, m1, 1));
    m1 = fmaxf(m1, __shfl_xor_sync(0xffffffffu, m1, 2));

    float s0 = 0.f, s1 = 0.f;
#pragma unroll
    for (int nt = 0; nt < 24; nt++) {
        sc[nt][0] = ex2(sc[nt][0] - m0);
        sc[nt][1] = ex2(sc[nt][1] - m0);
        sc[nt][2] = ex2(sc[nt][2] - m1);
        sc[nt][3] = ex2(sc[nt][3] - m1);
        s0 += sc[nt][0] + sc[nt][1];
        s1 += sc[nt][2] + sc[nt][3];
    }
    s0 += __shfl_xor_sync(0xffffffffu, s0, 1);
    s0 += __shfl_xor_sync(0xffffffffu, s0, 2);
    s1 += __shfl_xor_sync(0xffffffffu, s1, 1);
    s1 += __shfl_xor_sync(0xffffffffu, s1, 2);
    const float inv0 = rcp(s0), inv1 = rcp(s1);

    // ---- O = P V ----
    float oa[8][4];
#pragma unroll
    for (int nt = 0; nt < 8; nt++)
#pragma unroll
        for (int r = 0; r < 4; r++) oa[nt][r] = 0.f;

#pragma unroll
    for (int kc = 0; kc < 12; kc++) {
        unsigned ph[4];
        ph[0] = packf16(sc[2 * kc][0],     sc[2 * kc][1]);
        ph[1] = packf16(sc[2 * kc][2],     sc[2 * kc][3]);
        ph[2] = packf16(sc[2 * kc + 1][0], sc[2 * kc + 1][1]);
        ph[3] = packf16(sc[2 * kc + 1][2], sc[2 * kc + 1][3]);
#pragma unroll
        for (int dt = 0; dt < 4; dt++) {
            unsigned vh[4];
            unsigned voff = (unsigned)((kc * 16 + (lane & 15)) * AROWB) + dt * 32 + ((lane >> 4) << 4);
            ldm_x4t(vh, sb + A_SV + voff);
            mma_f16(oa[2 * dt],     ph, &vh[0]);
            mma_f16(oa[2 * dt + 1], ph, &vh[2]);
        }
    }

    // ---- normalize + write ctx as fp16 ----
    const int row0 = q0 + w * 16 + er;
#pragma unroll
    for (int nt = 0; nt < 8; nt++) {
        const int oc = col + nt * 8 + ec;
        float v0 = oa[nt][0] * inv0, v1 = oa[nt][1] * inv0;
        float v2 = oa[nt][2] * inv1, v3 = oa[nt][3] * inv1;
        *(unsigned*)&g_c16[(size_t)row0 * DMODEL + oc] = packf16(v0, v1);
        *(unsigned*)&g_c16[(size_t)(row0 + 8) * DMODEL + oc] = packf16(v2, v3);
    }
}

// ---------------- launch ----------------
extern "C" void kernel_launch(void* const* d_in, const int* in_sizes, int n_in,
                              void* d_out, int out_size)
{
    const float* x  = (const float*)d_in[0];
    const float* Wq = (const float*)d_in[1];
    const float* bq = (const float*)d_in[2];
    const float* Wk = (const float*)d_in[3];
    const float* bk = (const float*)d_in[4];
    const float* Wv = (const float*)d_in[5];
    const float* bv = (const float*)d_in[6];
    const float* Wo = (const float*)d_in[7];
    const float* bo = (const float*)d_in[8];
    float* out = (float*)d_out;

    unsigned short* x16;
    cudaGetSymbolAddress((void**)&x16, g_x16);

    cudaFuncSetAttribute(gemm_qkv, cudaFuncAttributeMaxDynamicSharedMemorySize, GSMEM);
    cudaFuncSetAttribute(gemm_out, cudaFuncAttributeMaxDynamicSharedMemorySize, GSMEM);
    cudaFuncSetAttribute(attn_mma, cudaFuncAttributeMaxDynamicSharedMemorySize, A_SMEM);

    to_f16<<<NX / 1024, 256>>>(x, x16);
    to_f16_w<<<4096, 256>>>(Wq, Wk, Wv, Wo);

    dim3 gq(24, 32);                       // fused Q,K,V
    gemm_qkv<<<gq, 256, GSMEM>>>(bq, bk, bv);

    dim3 ga(S_LEN / AT_Q, N_HEADS);        // (64, 16)
    attn_mma<<<ga, 128, A_SMEM>>>();

    dim3 go(8, 32);
    gemm_out<<<go, 256, GSMEM>>>(bo, out);
}

// round 10
// speedup vs baseline: 6.7458x; 1.0776x over previous
#include <cuda_runtime.h>
#include <cuda_fp16.h>
#include <math.h>

// ---------------- problem constants ----------------
#define S_LEN    4096
#define DMODEL   1024
#define N_HEADS  16
#define HEAD_DIM 64
#define NX (S_LEN * DMODEL)
#define NW (DMODEL * DMODEL)

// ---------------- scratch: single-plane fp16 ----------------
__device__ unsigned short g_x16[NX];
__device__ unsigned short g_q16[NX];
__device__ unsigned short g_k16[NX];
__device__ unsigned short g_v16[NX];
__device__ unsigned short g_c16[NX];
__device__ unsigned short g_Wq16[NW];
__device__ unsigned short g_Wk16[NW];
__device__ unsigned short g_Wv16[NW];
__device__ unsigned short g_Wo16[NW];

// ---------------- small helpers ----------------
__device__ __forceinline__ unsigned smem_u32(const void* p) {
    unsigned a;
    asm("{ .reg .u64 t; cvta.to.shared.u64 t, %1; cvt.u32.u64 %0, t; }" : "=r"(a) : "l"(p));
    return a;
}
__device__ __forceinline__ void cp16(unsigned dst, const void* src) {
    asm volatile("cp.async.cg.shared.global [%0], [%1], 16;" :: "r"(dst), "l"(src));
}
__device__ __forceinline__ void ldm_x4(unsigned* r, unsigned addr) {
    asm volatile("ldmatrix.sync.aligned.m8n8.x4.shared.b16 {%0,%1,%2,%3}, [%4];"
                 : "=r"(r[0]), "=r"(r[1]), "=r"(r[2]), "=r"(r[3]) : "r"(addr));
}
__device__ __forceinline__ void ldm_x4t(unsigned* r, unsigned addr) {
    asm volatile("ldmatrix.sync.aligned.m8n8.x4.trans.shared.b16 {%0,%1,%2,%3}, [%4];"
                 : "=r"(r[0]), "=r"(r[1]), "=r"(r[2]), "=r"(r[3]) : "r"(addr));
}
__device__ __forceinline__ void mma_f16(float* d, const unsigned* a, const unsigned* b) {
    asm volatile(
        "mma.sync.aligned.m16n8k16.row.col.f32.f16.f16.f32 "
        "{%0,%1,%2,%3}, {%4,%5,%6,%7}, {%8,%9}, {%0,%1,%2,%3};"
        : "+f"(d[0]), "+f"(d[1]), "+f"(d[2]), "+f"(d[3])
        : "r"(a[0]), "r"(a[1]), "r"(a[2]), "r"(a[3]), "r"(b[0]), "r"(b[1]));
}
__device__ __forceinline__ unsigned packf16(float lo, float hi) {
    unsigned r;
    asm("cvt.rn.f16x2.f32 %0, %1, %2;" : "=r"(r) : "f"(hi), "f"(lo));
    return r;
}
__device__ __forceinline__ float ex2(float x) {
    float y; asm("ex2.approx.ftz.f32 %0, %1;" : "=f"(y) : "f"(x)); return y;
}
__device__ __forceinline__ float rcp(float x) {
    float y; asm("rcp.approx.ftz.f32 %0, %1;" : "=f"(y) : "f"(x)); return y;
}

// ---------------- convert fp32 -> fp16 (x + 4 weight matrices, one launch) ----------------
__global__ __launch_bounds__(256)
void to_f16_all(const float* __restrict__ x,
                const float* __restrict__ wq, const float* __restrict__ wk,
                const float* __restrict__ wv, const float* __restrict__ wo)
{
    const int b = blockIdx.x;
    const float* src;
    unsigned short* dst;
    int i;
    if (b < 4096) {
        src = x; dst = g_x16;
        i = (b * 256 + threadIdx.x) * 4;
    } else {
        const int wsel = (b - 4096) >> 10;
        src = (wsel == 0) ? wq : (wsel == 1) ? wk : (wsel == 2) ? wv : wo;
        dst = (wsel == 0) ? g_Wq16 : (wsel == 1) ? g_Wk16 : (wsel == 2) ? g_Wv16 : g_Wo16;
        i = (((b - 4096) & 1023) * 256 + threadIdx.x) * 4;
    }
    float4 a = *(const float4*)(src + i);
    *(uint2*)(dst + i) = make_uint2(packf16(a.x, a.y), packf16(a.z, a.w));
}

// ---------------- fp16 GEMM: C = A @ B^T + bias ----------------
// 128x128 tile, BK=32, 8 warps (2x4), warp tile 64x32, 3-stage cp.async, 2 CTAs/SM.
#define ROWB   80
#define PLANE  (128 * ROWB)              // 10240
#define STAGE  (2 * PLANE)               // 20480 (A + B)
#define NSTAGE 3
#define GSMEM  (NSTAGE * STAGE)          // 61440
#define NCHUNK 32

__device__ __forceinline__
void gemm_body(char* smem,
               const unsigned short* __restrict__ A, const unsigned short* __restrict__ B,
               const float* __restrict__ bias, int bm, int bn,
               int mode, float* __restrict__ C, unsigned short* __restrict__ Ch)
{
    const int t = threadIdx.x, lane = t & 31, wid = t >> 5;
    const int wm = wid >> 2, wn = wid & 3;

    float acc[4][4][4];
#pragma unroll
    for (int mt = 0; mt < 4; mt++)
#pragma unroll
        for (int nt = 0; nt < 4; nt++)
#pragma unroll
            for (int r = 0; r < 4; r++) acc[mt][nt][r] = 0.f;

    const int r0 = t >> 2, s0 = t & 3;
    const int r1 = r0 + 64;

#define ISSUE(cc)                                                                 \
    {                                                                             \
        char* sb = smem + ((cc) % NSTAGE) * STAGE;                                \
        const int gk = (cc) * 32 + s0 * 8;                                        \
        const unsigned short* ga = A + (size_t)(bm + r0) * DMODEL + gk;           \
        const unsigned short* gb = B + (size_t)(bn + r0) * DMODEL + gk;           \
        unsigned da = smem_u32(sb + s0 * 16);                                     \
        unsigned db = smem_u32(sb + PLANE + s0 * 16);                             \
        cp16(da + r0 * ROWB, ga);                                                 \
        cp16(da + r1 * ROWB, ga + (size_t)64 * DMODEL);                           \
        cp16(db + r0 * ROWB, gb);                                                 \
        cp16(db + r1 * ROWB, gb + (size_t)64 * DMODEL);                           \
        asm volatile("cp.async.commit_group;" ::: "memory");                      \
    }

    ISSUE(0); ISSUE(1); ISSUE(2);

    const int a_row = wm * 64 + (lane & 15);
    const unsigned a_coff = (lane >> 4) * 16;
    const int b_row = wn * 32 + (lane & 7) + ((lane >> 4) << 3);
    const unsigned b_coff = ((lane >> 3) & 1) * 16;

    for (int c = 0; c < NCHUNK; c++) {
        if (c + 3 <= NCHUNK) {
            asm volatile("cp.async.wait_group 2;" ::: "memory");
        } else if (c + 2 <= NCHUNK) {
            asm volatile("cp.async.wait_group 1;" ::: "memory");
        } else {
            asm volatile("cp.async.wait_group 0;" ::: "memory");
        }
        __syncthreads();

        char* sb = smem + (c % NSTAGE) * STAGE;
        const unsigned sA = smem_u32(sb);
        const unsigned sB = sA + PLANE;

#pragma unroll
        for (int ks = 0; ks < 2; ks++) {
            const unsigned ka = ks * 32;
            unsigned bfr[2][4];
#pragma unroll
            for (int pr = 0; pr < 2; pr++)
                ldm_x4(bfr[pr], sB + (unsigned)((b_row + pr * 16) * ROWB) + ka + b_coff);
#pragma unroll
            for (int mt = 0; mt < 4; mt++) {
                unsigned afr[4];
                ldm_x4(afr, sA + (unsigned)((a_row + mt * 16) * ROWB) + ka + a_coff);
#pragma unroll
                for (int pr = 0; pr < 2; pr++)
#pragma unroll
                    for (int half = 0; half < 2; half++)
                        mma_f16(acc[mt][pr * 2 + half], afr, &bfr[pr][half * 2]);
            }
        }
        __syncthreads();
        if (c + 3 < NCHUNK) ISSUE(c + 3);
    }
#undef ISSUE

    // ---- epilogue ----
    const int er = lane >> 2, ec = (lane & 3) * 2;
#pragma unroll
    for (int mt = 0; mt < 4; mt++) {
        const int row = bm + wm * 64 + mt * 16 + er;
#pragma unroll
        for (int nt = 0; nt < 4; nt++) {
            const int col = bn + wn * 32 + nt * 8 + ec;
            const float b0 = bias[col], b1 = bias[col + 1];
            float v0 = acc[mt][nt][0] + b0, v1 = acc[mt][nt][1] + b1;
            float v2 = acc[mt][nt][2] + b0, v3 = acc[mt][nt][3] + b1;
            if (mode == 0) {
                *(float2*)&C[(size_t)row * DMODEL + col] = make_float2(v0, v1);
                *(float2*)&C[(size_t)(row + 8) * DMODEL + col] = make_float2(v2, v3);
            } else {
                *(unsigned*)&Ch[(size_t)row * DMODEL + col] = packf16(v0, v1);
                *(unsigned*)&Ch[(size_t)(row + 8) * DMODEL + col] = packf16(v2, v3);
            }
        }
    }
}

// ---- fused QKV projection: grid (24, 32); blockIdx.x/8 selects Q/K/V ----
__global__ __launch_bounds__(256, 2)
void gemm_qkv(const float* __restrict__ bq, const float* __restrict__ bk,
              const float* __restrict__ bv)
{
    extern __shared__ char smem[];
    const int which = blockIdx.x >> 3;
    const int bn = (blockIdx.x & 7) * 128;
    const int bm = blockIdx.y * 128;
    const unsigned short* B = (which == 0) ? g_Wq16 : (which == 1) ? g_Wk16 : g_Wv16;
    const float* bias = (which == 0) ? bq : (which == 1) ? bk : bv;
    unsigned short* Ch = (which == 0) ? g_q16 : (which == 1) ? g_k16 : g_v16;
    gemm_body(smem, g_x16, B, bias, bm, bn, 1, nullptr, Ch);
}

// ---- output projection: ctx(f16) @ Wo^T + bo -> fp32 out ----
__global__ __launch_bounds__(256, 2)
void gemm_out(const float* __restrict__ bo, float* __restrict__ out)
{
    extern __shared__ char smem[];
    gemm_body(smem, g_c16, g_Wo16, bo,
              blockIdx.y * 128, blockIdx.x * 128, 0, out, nullptr);
}

// ---------------- tensorized sliding-window attention (fp16) ----------------
// grid (S/128, H), 256 threads (8 warps). Warp w: 16 query rows (local 16w..16w+15),
// keys local [16w, 16w+143] of a shared 256-row K/V tile (9 pr-tiles of 16).
#define AT_Q   128
#define AT_KW  256
#define AROWB  144
#define A_SQ   0
#define A_SK   (AT_Q * AROWB)               // 18432
#define A_SV   (A_SK + AT_KW * AROWB)       // 55296
#define A_SMEM (A_SV + AT_KW * AROWB)       // 92160 -> 2 CTAs/SM

__global__ __launch_bounds__(256, 2)
void attn_mma()
{
    extern __shared__ char smem[];
    const unsigned sb = smem_u32(smem);
    const int t = threadIdx.x, lane = t & 31, w = t >> 5;
    const int h = blockIdx.y;
    const int q0 = blockIdx.x * AT_Q;
    const int j0 = q0 - 64;
    const int col = h * HEAD_DIM;

    // ---- load Q (128x64) ----
#pragma unroll
    for (int i = 0; i < 4; i++) {
        int idx = t + i * 256;               // 0..1023
        int r = idx >> 3, sg = idx & 7;
        *(uint4*)(smem + A_SQ + r * AROWB + sg * 16) =
            *(const uint4*)(g_q16 + (size_t)(q0 + r) * DMODEL + col + sg * 8);
    }
    // ---- load K,V window (256x64), zero-fill out of range ----
#pragma unroll
    for (int i = 0; i < 8; i++) {
        int idx = t + i * 256;               // 0..2047
        int r = idx >> 3, sg = idx & 7;
        int j = j0 + r;
        uint4 kv = make_uint4(0,0,0,0), vv = kv;
        if ((unsigned)j < (unsigned)S_LEN) {
            size_t go = (size_t)j * DMODEL + col + sg * 8;
            kv = *(const uint4*)(g_k16 + go);
            vv = *(const uint4*)(g_v16 + go);
        }
        unsigned so = r * AROWB + sg * 16;
        *(uint4*)(smem + A_SK + so) = kv;
        *(uint4*)(smem + A_SV + so) = vv;
    }
    __syncthreads();

    // ---- S = Q K^T over warp's 144-key window ----
    float sc[18][4];
#pragma unroll
    for (int nt = 0; nt < 18; nt++)
#pragma unroll
        for (int r = 0; r < 4; r++) sc[nt][r] = 0.f;

    const int lk0 = w * 16;
    const unsigned a_base = (unsigned)((w * 16 + (lane & 15)) * AROWB) + ((lane >> 4) << 4);
    const int b_lrow = (lane & 7) + ((lane >> 4) << 3);
    const unsigned b_coff = ((lane >> 3) & 1) << 4;

#pragma unroll
    for (int kc = 0; kc < 4; kc++) {
        unsigned afr[4];
        ldm_x4(afr, sb + A_SQ + a_base + kc * 32);
#pragma unroll
        for (int pr = 0; pr < 9; pr++) {
            unsigned bfr[4];
            ldm_x4(bfr, sb + A_SK + (unsigned)((lk0 + pr * 16 + b_lrow) * AROWB) + kc * 32 + b_coff);
            mma_f16(sc[pr * 2],     afr, &bfr[0]);
            mma_f16(sc[pr * 2 + 1], afr, &bfr[2]);
        }
    }

    // ---- mask + softmax ----
    // key local (in warp window) d = nt*8+ec; query row offset er (and er+8).
    // valid iff d - er in [0,128] (warp-invariant) and global j in range.
    const int er = lane >> 2, ec = (lane & 3) * 2;
    const float SC = 0.125f * 1.44269504088896f;
    float m0 = -1e30f, m1 = -1e30f;
#pragma unroll
    for (int nt = 0; nt < 18; nt++) {
        const int d = nt * 8 + ec;
        const int j = j0 + lk0 + d;
        bool v00 = ((unsigned)(d     - er)     <= 128u) && ((unsigned)j       < (unsigned)S_LEN);
        bool v01 = ((unsigned)(d + 1 - er)     <= 128u) && ((unsigned)(j + 1) < (unsigned)S_LEN);
        bool v10 = ((unsigned)(d     - er - 8) <= 128u) && ((unsigned)j       < (unsigned)S_LEN);
        bool v11 = ((unsigned)(d + 1 - er - 8) <= 128u) && ((unsigned)(j + 1) < (unsigned)S_LEN);
        sc[nt][0] = v00 ? sc[nt][0] * SC : -1e30f;
        sc[nt][1] = v01 ? sc[nt][1] * SC : -1e30f;
        sc[nt][2] = v10 ? sc[nt][2] * SC : -1e30f;
        sc[nt][3] = v11 ? sc[nt][3] * SC : -1e30f;
        m0 = fmaxf(m0, fmaxf(sc[nt][0], sc[nt][1]));
        m1 = fmaxf(m1, fmaxf(sc[nt][2], sc[nt][3]));
    }
    m0 = fmaxf(m0, __shfl_xor_sync(0xffffffffu, m0, 1));
    m0 = fmaxf(m0, __shfl_xor_sync(0xffffffffu, m0, 2));
    m1 = fmaxf(m1, __shfl_xor_sync(0xffffffffu, m1, 1));
    m1 = fmaxf(m1, __shfl_xor_sync(0xffffffffu, m1, 2));

    float s0 = 0.f, s1 = 0.f;
#pragma unroll
    for (int nt = 0; nt < 18; nt++) {
        sc[nt][0] = ex2(sc[nt][0] - m0);
        sc[nt][1] = ex2(sc[nt][1] - m0);
        sc[nt][2] = ex2(sc[nt][2] - m1);
        sc[nt][3] = ex2(sc[nt][3] - m1);
        s0 += sc[nt][0] + sc[nt][1];
        s1 += sc[nt][2] + sc[nt][3];
    }
    s0 += __shfl_xor_sync(0xffffffffu, s0, 1);
    s0 += __shfl_xor_sync(0xffffffffu, s0, 2);
    s1 += __shfl_xor_sync(0xffffffffu, s1, 1);
    s1 += __shfl_xor_sync(0xffffffffu, s1, 2);
    const float inv0 = rcp(s0), inv1 = rcp(s1);

    // ---- O = P V over the same 144-key window ----
    float oa[8][4];
#pragma unroll
    for (int nt = 0; nt < 8; nt++)
#pragma unroll
        for (int r = 0; r < 4; r++) oa[nt][r] = 0.f;

#pragma unroll
    for (int kc = 0; kc < 9; kc++) {
        unsigned ph[4];
        ph[0] = packf16(sc[2 * kc][0],     sc[2 * kc][1]);
        ph[1] = packf16(sc[2 * kc][2],     sc[2 * kc][3]);
        ph[2] = packf16(sc[2 * kc + 1][0], sc[2 * kc + 1][1]);
        ph[3] = packf16(sc[2 * kc + 1][2], sc[2 * kc + 1][3]);
#pragma unroll
        for (int dt = 0; dt < 4; dt++) {
            unsigned vh[4];
            unsigned voff = (unsigned)((lk0 + kc * 16 + (lane & 15)) * AROWB) + dt * 32 + ((lane >> 4) << 4);
            ldm_x4t(vh, sb + A_SV + voff);
            mma_f16(oa[2 * dt],     ph, &vh[0]);
            mma_f16(oa[2 * dt + 1], ph, &vh[2]);
        }
    }

    // ---- normalize + write ctx as fp16 ----
    const int row0 = q0 + w * 16 + er;
#pragma unroll
    for (int nt = 0; nt < 8; nt++) {
        const int oc = col + nt * 8 + ec;
        float v0 = oa[nt][0] * inv0, v1 = oa[nt][1] * inv0;
        float v2 = oa[nt][2] * inv1, v3 = oa[nt][3] * inv1;
        *(unsigned*)&g_c16[(size_t)row0 * DMODEL + oc] = packf16(v0, v1);
        *(unsigned*)&g_c16[(size_t)(row0 + 8) * DMODEL + oc] = packf16(v2, v3);
    }
}

// ---------------- launch ----------------
extern "C" void kernel_launch(void* const* d_in, const int* in_sizes, int n_in,
                              void* d_out, int out_size)
{
    const float* x  = (const float*)d_in[0];
    const float* Wq = (const float*)d_in[1];
    const float* bq = (const float*)d_in[2];
    const float* Wk = (const float*)d_in[3];
    const float* bk = (const float*)d_in[4];
    const float* Wv = (const float*)d_in[5];
    const float* bv = (const float*)d_in[6];
    const float* Wo = (const float*)d_in[7];
    const float* bo = (const float*)d_in[8];
    float* out = (float*)d_out;

    cudaFuncSetAttribute(gemm_qkv, cudaFuncAttributeMaxDynamicSharedMemorySize, GSMEM);
    cudaFuncSetAttribute(gemm_out, cudaFuncAttributeMaxDynamicSharedMemorySize, GSMEM);
    cudaFuncSetAttribute(attn_mma, cudaFuncAttributeMaxDynamicSharedMemorySize, A_SMEM);

    to_f16_all<<<8192, 256>>>(x, Wq, Wk, Wv, Wo);

    dim3 gq(24, 32);                       // fused Q,K,V
    gemm_qkv<<<gq, 256, GSMEM>>>(bq, bk, bv);

    dim3 ga(S_LEN / AT_Q, N_HEADS);        // (32, 16)
    attn_mma<<<ga, 256, A_SMEM>>>();

    dim3 go(8, 32);
    gemm_out<<<go, 256, GSMEM>>>(bo, out);
}

// round 11
// speedup vs baseline: 7.0993x; 1.0524x over previous
#include <cuda_runtime.h>
#include <cuda_fp16.h>
#include <math.h>

// ---------------- problem constants ----------------
#define S_LEN    4096
#define DMODEL   1024
#define N_HEADS  16
#define HEAD_DIM 64
#define NX (S_LEN * DMODEL)
#define NW (DMODEL * DMODEL)

// ---------------- scratch: single-plane fp16 ----------------
__device__ unsigned short g_x16[NX];
__device__ unsigned short g_q16[NX];
__device__ unsigned short g_k16[NX];
__device__ unsigned short g_v16[NX];
__device__ unsigned short g_c16[NX];
__device__ unsigned short g_Wq16[NW];
__device__ unsigned short g_Wk16[NW];
__device__ unsigned short g_Wv16[NW];
__device__ unsigned short g_Wo16[NW];

// ---------------- small helpers ----------------
__device__ __forceinline__ unsigned smem_u32(const void* p) {
    unsigned a;
    asm("{ .reg .u64 t; cvta.to.shared.u64 t, %1; cvt.u32.u64 %0, t; }" : "=r"(a) : "l"(p));
    return a;
}
__device__ __forceinline__ void cp16(unsigned dst, const void* src) {
    asm volatile("cp.async.cg.shared.global [%0], [%1], 16;" :: "r"(dst), "l"(src));
}
__device__ __forceinline__ void ldm_x4(unsigned* r, unsigned addr) {
    asm volatile("ldmatrix.sync.aligned.m8n8.x4.shared.b16 {%0,%1,%2,%3}, [%4];"
                 : "=r"(r[0]), "=r"(r[1]), "=r"(r[2]), "=r"(r[3]) : "r"(addr));
}
__device__ __forceinline__ void ldm_x4t(unsigned* r, unsigned addr) {
    asm volatile("ldmatrix.sync.aligned.m8n8.x4.trans.shared.b16 {%0,%1,%2,%3}, [%4];"
                 : "=r"(r[0]), "=r"(r[1]), "=r"(r[2]), "=r"(r[3]) : "r"(addr));
}
__device__ __forceinline__ void mma_f16(float* d, const unsigned* a, const unsigned* b) {
    asm volatile(
        "mma.sync.aligned.m16n8k16.row.col.f32.f16.f16.f32 "
        "{%0,%1,%2,%3}, {%4,%5,%6,%7}, {%8,%9}, {%0,%1,%2,%3};"
        : "+f"(d[0]), "+f"(d[1]), "+f"(d[2]), "+f"(d[3])
        : "r"(a[0]), "r"(a[1]), "r"(a[2]), "r"(a[3]), "r"(b[0]), "r"(b[1]));
}
__device__ __forceinline__ unsigned packf16(float lo, float hi) {
    unsigned r;
    asm("cvt.rn.f16x2.f32 %0, %1, %2;" : "=r"(r) : "f"(hi), "f"(lo));
    return r;
}
__device__ __forceinline__ float ex2(float x) {
    float y; asm("ex2.approx.ftz.f32 %0, %1;" : "=f"(y) : "f"(x)); return y;
}
__device__ __forceinline__ float rcp(float x) {
    float y; asm("rcp.approx.ftz.f32 %0, %1;" : "=f"(y) : "f"(x)); return y;
}

// ---------------- convert fp32 -> fp16 (x + 4 weight matrices, one launch) ----------------
__global__ __launch_bounds__(256)
void to_f16_all(const float* __restrict__ x,
                const float* __restrict__ wq, const float* __restrict__ wk,
                const float* __restrict__ wv, const float* __restrict__ wo)
{
    const int b = blockIdx.x;
    const float* src;
    unsigned short* dst;
    int i;
    if (b < 4096) {
        src = x; dst = g_x16;
        i = (b * 256 + threadIdx.x) * 4;
    } else {
        const int wsel = (b - 4096) >> 10;
        src = (wsel == 0) ? wq : (wsel == 1) ? wk : (wsel == 2) ? wv : wo;
        dst = (wsel == 0) ? g_Wq16 : (wsel == 1) ? g_Wk16 : (wsel == 2) ? g_Wv16 : g_Wo16;
        i = (((b - 4096) & 1023) * 256 + threadIdx.x) * 4;
    }
    float4 a = *(const float4*)(src + i);
    *(uint2*)(dst + i) = make_uint2(packf16(a.x, a.y), packf16(a.z, a.w));
}

// ---------------- fp16 GEMM: C = A @ B^T + bias ----------------
// 128x128 tile, BK=32, 8 warps (2x4), warp tile 64x32.
// 4-stage cp.async, ONE __syncthreads per chunk, 2 CTAs/SM.
#define ROWB   80
#define PLANE  (128 * ROWB)              // 10240
#define STAGE  (2 * PLANE)               // 20480 (A + B)
#define NSTAGE 4
#define GSMEM  (NSTAGE * STAGE)          // 81920
#define NCHUNK 32

__device__ __forceinline__
void gemm_body(char* smem,
               const unsigned short* __restrict__ A, const unsigned short* __restrict__ B,
               const float* __restrict__ bias, int bm, int bn,
               int mode, float* __restrict__ C, unsigned short* __restrict__ Ch)
{
    const int t = threadIdx.x, lane = t & 31, wid = t >> 5;
    const int wm = wid >> 2, wn = wid & 3;

    float acc[4][4][4];
#pragma unroll
    for (int mt = 0; mt < 4; mt++)
#pragma unroll
        for (int nt = 0; nt < 4; nt++)
#pragma unroll
            for (int r = 0; r < 4; r++) acc[mt][nt][r] = 0.f;

    const int r0 = t >> 2, s0 = t & 3;
    const int r1 = r0 + 64;

#define ISSUE(cc)                                                                 \
    {                                                                             \
        char* sb = smem + ((cc) & (NSTAGE - 1)) * STAGE;                          \
        const int gk = (cc) * 32 + s0 * 8;                                        \
        const unsigned short* ga = A + (size_t)(bm + r0) * DMODEL + gk;           \
        const unsigned short* gb = B + (size_t)(bn + r0) * DMODEL + gk;           \
        unsigned da = smem_u32(sb + s0 * 16);                                     \
        unsigned db = smem_u32(sb + PLANE + s0 * 16);                             \
        cp16(da + r0 * ROWB, ga);                                                 \
        cp16(da + r1 * ROWB, ga + (size_t)64 * DMODEL);                           \
        cp16(db + r0 * ROWB, gb);                                                 \
        cp16(db + r1 * ROWB, gb + (size_t)64 * DMODEL);                           \
        asm volatile("cp.async.commit_group;" ::: "memory");                      \
    }

    ISSUE(0); ISSUE(1); ISSUE(2);

    const int a_row = wm * 64 + (lane & 15);
    const unsigned a_coff = (lane >> 4) * 16;
    const int b_row = wn * 32 + (lane & 7) + ((lane >> 4) << 3);
    const unsigned b_coff = ((lane >> 3) & 1) * 16;

    for (int c = 0; c < NCHUNK; c++) {
        // ensure stage c has arrived (2 groups may remain pending in steady state)
        if (c + 3 <= NCHUNK) {
            asm volatile("cp.async.wait_group 2;" ::: "memory");
        } else if (c + 2 <= NCHUNK) {
            asm volatile("cp.async.wait_group 1;" ::: "memory");
        } else {
            asm volatile("cp.async.wait_group 0;" ::: "memory");
        }
        __syncthreads();   // all warps done reading buffer (c-1)%4 AND stage c visible

        // refill buffer (c+3)%4 == buffer of (c-1), protected by the barrier above
        if (c + 3 < NCHUNK) ISSUE(c + 3);

        char* sb = smem + (c & (NSTAGE - 1)) * STAGE;
        const unsigned sA = smem_u32(sb);
        const unsigned sB = sA + PLANE;

#pragma unroll
        for (int ks = 0; ks < 2; ks++) {
            const unsigned ka = ks * 32;
            unsigned bfr[2][4];
#pragma unroll
            for (int pr = 0; pr < 2; pr++)
                ldm_x4(bfr[pr], sB + (unsigned)((b_row + pr * 16) * ROWB) + ka + b_coff);
#pragma unroll
            for (int mt = 0; mt < 4; mt++) {
                unsigned afr[4];
                ldm_x4(afr, sA + (unsigned)((a_row + mt * 16) * ROWB) + ka + a_coff);
#pragma unroll
                for (int pr = 0; pr < 2; pr++)
#pragma unroll
                    for (int half = 0; half < 2; half++)
                        mma_f16(acc[mt][pr * 2 + half], afr, &bfr[pr][half * 2]);
            }
        }
    }
#undef ISSUE

    // ---- epilogue ----
    const int er = lane >> 2, ec = (lane & 3) * 2;
#pragma unroll
    for (int mt = 0; mt < 4; mt++) {
        const int row = bm + wm * 64 + mt * 16 + er;
#pragma unroll
        for (int nt = 0; nt < 4; nt++) {
            const int col = bn + wn * 32 + nt * 8 + ec;
            const float b0 = bias[col], b1 = bias[col + 1];
            float v0 = acc[mt][nt][0] + b0, v1 = acc[mt][nt][1] + b1;
            float v2 = acc[mt][nt][2] + b0, v3 = acc[mt][nt][3] + b1;
            if (mode == 0) {
                *(float2*)&C[(size_t)row * DMODEL + col] = make_float2(v0, v1);
                *(float2*)&C[(size_t)(row + 8) * DMODEL + col] = make_float2(v2, v3);
            } else {
                *(unsigned*)&Ch[(size_t)row * DMODEL + col] = packf16(v0, v1);
                *(unsigned*)&Ch[(size_t)(row + 8) * DMODEL + col] = packf16(v2, v3);
            }
        }
    }
}

// ---- fused QKV projection: grid (24, 32); blockIdx.x/8 selects Q/K/V ----
__global__ __launch_bounds__(256, 2)
void gemm_qkv(const float* __restrict__ bq, const float* __restrict__ bk,
              const float* __restrict__ bv)
{
    extern __shared__ char smem[];
    const int which = blockIdx.x >> 3;
    const int bn = (blockIdx.x & 7) * 128;
    const int bm = blockIdx.y * 128;
    const unsigned short* B = (which == 0) ? g_Wq16 : (which == 1) ? g_Wk16 : g_Wv16;
    const float* bias = (which == 0) ? bq : (which == 1) ? bk : bv;
    unsigned short* Ch = (which == 0) ? g_q16 : (which == 1) ? g_k16 : g_v16;
    gemm_body(smem, g_x16, B, bias, bm, bn, 1, nullptr, Ch);
}

// ---- output projection: ctx(f16) @ Wo^T + bo -> fp32 out ----
__global__ __launch_bounds__(256, 2)
void gemm_out(const float* __restrict__ bo, float* __restrict__ out)
{
    extern __shared__ char smem[];
    gemm_body(smem, g_c16, g_Wo16, bo,
              blockIdx.y * 128, blockIdx.x * 128, 0, out, nullptr);
}

// ---------------- tensorized sliding-window attention (fp16) ----------------
// grid (S/128, H), 256 threads (8 warps). Warp w: 16 query rows (local 16w..16w+15),
// keys local [16w, 16w+143] of a shared 256-row K/V tile (9 pr-tiles of 16).
#define AT_Q   128
#define AT_KW  256
#define AROWB  144
#define A_SQ   0
#define A_SK   (AT_Q * AROWB)               // 18432
#define A_SV   (A_SK + AT_KW * AROWB)       // 55296
#define A_SMEM (A_SV + AT_KW * AROWB)       // 92160 -> 2 CTAs/SM

__global__ __launch_bounds__(256, 2)
void attn_mma()
{
    extern __shared__ char smem[];
    const unsigned sb = smem_u32(smem);
    const int t = threadIdx.x, lane = t & 31, w = t >> 5;
    const int h = blockIdx.y;
    const int q0 = blockIdx.x * AT_Q;
    const int j0 = q0 - 64;
    const int col = h * HEAD_DIM;

    // ---- load Q (128x64) ----
#pragma unroll
    for (int i = 0; i < 4; i++) {
        int idx = t + i * 256;               // 0..1023
        int r = idx >> 3, sg = idx & 7;
        *(uint4*)(smem + A_SQ + r * AROWB + sg * 16) =
            *(const uint4*)(g_q16 + (size_t)(q0 + r) * DMODEL + col + sg * 8);
    }
    // ---- load K,V window (256x64), zero-fill out of range ----
#pragma unroll
    for (int i = 0; i < 8; i++) {
        int idx = t + i * 256;               // 0..2047
        int r = idx >> 3, sg = idx & 7;
        int j = j0 + r;
        uint4 kv = make_uint4(0,0,0,0), vv = kv;
        if ((unsigned)j < (unsigned)S_LEN) {
            size_t go = (size_t)j * DMODEL + col + sg * 8;
            kv = *(const uint4*)(g_k16 + go);
            vv = *(const uint4*)(g_v16 + go);
        }
        unsigned so = r * AROWB + sg * 16;
        *(uint4*)(smem + A_SK + so) = kv;
        *(uint4*)(smem + A_SV + so) = vv;
    }
    __syncthreads();

    // ---- S = Q K^T over warp's 144-key window ----
    float sc[18][4];
#pragma unroll
    for (int nt = 0; nt < 18; nt++)
#pragma unroll
        for (int r = 0; r < 4; r++) sc[nt][r] = 0.f;

    const int lk0 = w * 16;
    const unsigned a_base = (unsigned)((w * 16 + (lane & 15)) * AROWB) + ((lane >> 4) << 4);
    const int b_lrow = (lane & 7) + ((lane >> 4) << 3);
    const unsigned b_coff = ((lane >> 3) & 1) << 4;

#pragma unroll
    for (int kc = 0; kc < 4; kc++) {
        unsigned afr[4];
        ldm_x4(afr, sb + A_SQ + a_base + kc * 32);
#pragma unroll
        for (int pr = 0; pr < 9; pr++) {
            unsigned bfr[4];
            ldm_x4(bfr, sb + A_SK + (unsigned)((lk0 + pr * 16 + b_lrow) * AROWB) + kc * 32 + b_coff);
            mma_f16(sc[pr * 2],     afr, &bfr[0]);
            mma_f16(sc[pr * 2 + 1], afr, &bfr[2]);
        }
    }

    // ---- mask + softmax ----
    const int er = lane >> 2, ec = (lane & 3) * 2;
    const float SC = 0.125f * 1.44269504088896f;
    float m0 = -1e30f, m1 = -1e30f;
#pragma unroll
    for (int nt = 0; nt < 18; nt++) {
        const int d = nt * 8 + ec;
        const int j = j0 + lk0 + d;
        bool v00 = ((unsigned)(d     - er)     <= 128u) && ((unsigned)j       < (unsigned)S_LEN);
        bool v01 = ((unsigned)(d + 1 - er)     <= 128u) && ((unsigned)(j + 1) < (unsigned)S_LEN);
        bool v10 = ((unsigned)(d     - er - 8) <= 128u) && ((unsigned)j       < (unsigned)S_LEN);
        bool v11 = ((unsigned)(d + 1 - er - 8) <= 128u) && ((unsigned)(j + 1) < (unsigned)S_LEN);
        sc[nt][0] = v00 ? sc[nt][0] * SC : -1e30f;
        sc[nt][1] = v01 ? sc[nt][1] * SC : -1e30f;
        sc[nt][2] = v10 ? sc[nt][2] * SC : -1e30f;
        sc[nt][3] = v11 ? sc[nt][3] * SC : -1e30f;
        m0 = fmaxf(m0, fmaxf(sc[nt][0], sc[nt][1]));
        m1 = fmaxf(m1, fmaxf(sc[nt][2], sc[nt][3]));
    }
    m0 = fmaxf(m0, __shfl_xor_sync(0xffffffffu, m0, 1));
    m0 = fmaxf(m0, __shfl_xor_sync(0xffffffffu, m0, 2));
    m1 = fmaxf(m1, __shfl_xor_sync(0xffffffffu, m1, 1));
    m1 = fmaxf(m1, __shfl_xor_sync(0xffffffffu, m1, 2));

    float s0 = 0.f, s1 = 0.f;
#pragma unroll
    for (int nt = 0; nt < 18; nt++) {
        sc[nt][0] = ex2(sc[nt][0] - m0);
        sc[nt][1] = ex2(sc[nt][1] - m0);
        sc[nt][2] = ex2(sc[nt][2] - m1);
        sc[nt][3] = ex2(sc[nt][3] - m1);
        s0 += sc[nt][0] + sc[nt][1];
        s1 += sc[nt][2] + sc[nt][3];
    }
    s0 += __shfl_xor_sync(0xffffffffu, s0, 1);
    s0 += __shfl_xor_sync(0xffffffffu, s0, 2);
    s1 += __shfl_xor_sync(0xffffffffu, s1, 1);
    s1 += __shfl_xor_sync(0xffffffffu, s1, 2);
    const float inv0 = rcp(s0), inv1 = rcp(s1);

    // ---- O = P V over the same 144-key window ----
    float oa[8][4];
#pragma unroll
    for (int nt = 0; nt < 8; nt++)
#pragma unroll
        for (int r = 0; r < 4; r++) oa[nt][r] = 0.f;

#pragma unroll
    for (int kc = 0; kc < 9; kc++) {
        unsigned ph[4];
        ph[0] = packf16(sc[2 * kc][0],     sc[2 * kc][1]);
        ph[1] = packf16(sc[2 * kc][2],     sc[2 * kc][3]);
        ph[2] = packf16(sc[2 * kc + 1][0], sc[2 * kc + 1][1]);
        ph[3] = packf16(sc[2 * kc + 1][2], sc[2 * kc + 1][3]);
#pragma unroll
        for (int dt = 0; dt < 4; dt++) {
            unsigned vh[4];
            unsigned voff = (unsigned)((lk0 + kc * 16 + (lane & 15)) * AROWB) + dt * 32 + ((lane >> 4) << 4);
            ldm_x4t(vh, sb + A_SV + voff);
            mma_f16(oa[2 * dt],     ph, &vh[0]);
            mma_f16(oa[2 * dt + 1], ph, &vh[2]);
        }
    }

    // ---- normalize + write ctx as fp16 ----
    const int row0 = q0 + w * 16 + er;
#pragma unroll
    for (int nt = 0; nt < 8; nt++) {
        const int oc = col + nt * 8 + ec;
        float v0 = oa[nt][0] * inv0, v1 = oa[nt][1] * inv0;
        float v2 = oa[nt][2] * inv1, v3 = oa[nt][3] * inv1;
        *(unsigned*)&g_c16[(size_t)row0 * DMODEL + oc] = packf16(v0, v1);
        *(unsigned*)&g_c16[(size_t)(row0 + 8) * DMODEL + oc] = packf16(v2, v3);
    }
}

// ---------------- launch ----------------
extern "C" void kernel_launch(void* const* d_in, const int* in_sizes, int n_in,
                              void* d_out, int out_size)
{
    const float* x  = (const float*)d_in[0];
    const float* Wq = (const float*)d_in[1];
    const float* bq = (const float*)d_in[2];
    const float* Wk = (const float*)d_in[3];
    const float* bk = (const float*)d_in[4];
    const float* Wv = (const float*)d_in[5];
    const float* bv = (const float*)d_in[6];
    const float* Wo = (const float*)d_in[7];
    const float* bo = (const float*)d_in[8];
    float* out = (float*)d_out;

    cudaFuncSetAttribute(gemm_qkv, cudaFuncAttributeMaxDynamicSharedMemorySize, GSMEM);
    cudaFuncSetAttribute(gemm_out, cudaFuncAttributeMaxDynamicSharedMemorySize, GSMEM);
    cudaFuncSetAttribute(attn_mma, cudaFuncAttributeMaxDynamicSharedMemorySize, A_SMEM);

    to_f16_all<<<8192, 256>>>(x, Wq, Wk, Wv, Wo);

    dim3 gq(24, 32);                       // fused Q,K,V
    gemm_qkv<<<gq, 256, GSMEM>>>(bq, bk, bv);

    dim3 ga(S_LEN / AT_Q, N_HEADS);        // (32, 16)
    attn_mma<<<ga, 256, A_SMEM>>>();

    dim3 go(8, 32);
    gemm_out<<<go, 256, GSMEM>>>(bo, out);
}

// round 12
// speedup vs baseline: 7.3773x; 1.0392x over previous
#include <cuda_runtime.h>
#include <cuda_fp16.h>
#include <math.h>

// ---------------- problem constants ----------------
#define S_LEN    4096
#define DMODEL   1024
#define N_HEADS  16
#define HEAD_DIM 64
#define NX (S_LEN * DMODEL)
#define NW (DMODEL * DMODEL)

// ---------------- scratch: single-plane fp16 ----------------
__device__ unsigned short g_x16[NX];
__device__ unsigned short g_q16[NX];
__device__ unsigned short g_k16[NX];
__device__ unsigned short g_v16[NX];
__device__ unsigned short g_c16[NX];
__device__ unsigned short g_Wq16[NW];
__device__ unsigned short g_Wk16[NW];
__device__ unsigned short g_Wv16[NW];
__device__ unsigned short g_Wo16[NW];

// ---------------- small helpers ----------------
__device__ __forceinline__ unsigned smem_u32(const void* p) {
    unsigned a;
    asm("{ .reg .u64 t; cvta.to.shared.u64 t, %1; cvt.u32.u64 %0, t; }" : "=r"(a) : "l"(p));
    return a;
}
__device__ __forceinline__ void cp16(unsigned dst, const void* src) {
    asm volatile("cp.async.cg.shared.global [%0], [%1], 16;" :: "r"(dst), "l"(src));
}
__device__ __forceinline__ void ldm_x4(unsigned* r, unsigned addr) {
    asm volatile("ldmatrix.sync.aligned.m8n8.x4.shared.b16 {%0,%1,%2,%3}, [%4];"
                 : "=r"(r[0]), "=r"(r[1]), "=r"(r[2]), "=r"(r[3]) : "r"(addr));
}
__device__ __forceinline__ void ldm_x4t(unsigned* r, unsigned addr) {
    asm volatile("ldmatrix.sync.aligned.m8n8.x4.trans.shared.b16 {%0,%1,%2,%3}, [%4];"
                 : "=r"(r[0]), "=r"(r[1]), "=r"(r[2]), "=r"(r[3]) : "r"(addr));
}
__device__ __forceinline__ void mma_f16(float* d, const unsigned* a, const unsigned* b) {
    asm volatile(
        "mma.sync.aligned.m16n8k16.row.col.f32.f16.f16.f32 "
        "{%0,%1,%2,%3}, {%4,%5,%6,%7}, {%8,%9}, {%0,%1,%2,%3};"
        : "+f"(d[0]), "+f"(d[1]), "+f"(d[2]), "+f"(d[3])
        : "r"(a[0]), "r"(a[1]), "r"(a[2]), "r"(a[3]), "r"(b[0]), "r"(b[1]));
}
__device__ __forceinline__ unsigned packf16(float lo, float hi) {
    unsigned r;
    asm("cvt.rn.f16x2.f32 %0, %1, %2;" : "=r"(r) : "f"(hi), "f"(lo));
    return r;
}
__device__ __forceinline__ float ex2(float x) {
    float y; asm("ex2.approx.ftz.f32 %0, %1;" : "=f"(y) : "f"(x)); return y;
}
__device__ __forceinline__ float rcp(float x) {
    float y; asm("rcp.approx.ftz.f32 %0, %1;" : "=f"(y) : "f"(x)); return y;
}

// ---------------- convert fp32 -> fp16 (x + 4 weight matrices, one launch) ----------------
__global__ __launch_bounds__(256)
void to_f16_all(const float* __restrict__ x,
                const float* __restrict__ wq, const float* __restrict__ wk,
                const float* __restrict__ wv, const float* __restrict__ wo)
{
    const int b = blockIdx.x;
    const float* src;
    unsigned short* dst;
    int i;
    if (b < 4096) {
        src = x; dst = g_x16;
        i = (b * 256 + threadIdx.x) * 4;
    } else {
        const int wsel = (b - 4096) >> 10;
        src = (wsel == 0) ? wq : (wsel == 1) ? wk : (wsel == 2) ? wv : wo;
        dst = (wsel == 0) ? g_Wq16 : (wsel == 1) ? g_Wk16 : (wsel == 2) ? g_Wv16 : g_Wo16;
        i = (((b - 4096) & 1023) * 256 + threadIdx.x) * 4;
    }
    float4 a = *(const float4*)(src + i);
    *(uint2*)(dst + i) = make_uint2(packf16(a.x, a.y), packf16(a.z, a.w));
}

// ---------------- fp16 GEMM: C = A @ B^T + bias ----------------
// 128x128 tile, BK=32, 8 warps (2x4), warp tile 64x32.
// 4-stage cp.async, single sync per chunk, register fragment double-buffering.
#define ROWB   80
#define PLANE  (128 * ROWB)              // 10240
#define STAGE  (2 * PLANE)               // 20480 (A + B)
#define NSTAGE 4
#define GSMEM  (NSTAGE * STAGE)          // 81920
#define NCHUNK 32

struct Frags {
    unsigned a[4][4];
    unsigned b[2][4];
};

__device__ __forceinline__
void load_frags(Frags& f, unsigned sA, unsigned sB, unsigned ka,
                int a_row, unsigned a_coff, int b_row, unsigned b_coff)
{
#pragma unroll
    for (int pr = 0; pr < 2; pr++)
        ldm_x4(f.b[pr], sB + (unsigned)((b_row + pr * 16) * ROWB) + ka + b_coff);
#pragma unroll
    for (int mt = 0; mt < 4; mt++)
        ldm_x4(f.a[mt], sA + (unsigned)((a_row + mt * 16) * ROWB) + ka + a_coff);
}

__device__ __forceinline__
void do_mma(float acc[4][4][4], const Frags& f)
{
#pragma unroll
    for (int mt = 0; mt < 4; mt++)
#pragma unroll
        for (int pr = 0; pr < 2; pr++)
#pragma unroll
            for (int half = 0; half < 2; half++)
                mma_f16(acc[mt][pr * 2 + half], f.a[mt], &f.b[pr][half * 2]);
}

__device__ __forceinline__
void gemm_body(char* smem,
               const unsigned short* __restrict__ A, const unsigned short* __restrict__ B,
               const float* __restrict__ bias, int bm, int bn,
               int mode, float* __restrict__ C, unsigned short* __restrict__ Ch)
{
    const int t = threadIdx.x, lane = t & 31, wid = t >> 5;
    const int wm = wid >> 2, wn = wid & 3;

    float acc[4][4][4];
#pragma unroll
    for (int mt = 0; mt < 4; mt++)
#pragma unroll
        for (int nt = 0; nt < 4; nt++)
#pragma unroll
            for (int r = 0; r < 4; r++) acc[mt][nt][r] = 0.f;

    const int r0 = t >> 2, s0 = t & 3;
    const int r1 = r0 + 64;

#define ISSUE(cc)                                                                 \
    {                                                                             \
        char* sbuf = smem + ((cc) & (NSTAGE - 1)) * STAGE;                        \
        const int gk = (cc) * 32 + s0 * 8;                                        \
        const unsigned short* ga = A + (size_t)(bm + r0) * DMODEL + gk;           \
        const unsigned short* gb = B + (size_t)(bn + r0) * DMODEL + gk;           \
        unsigned da = smem_u32(sbuf + s0 * 16);                                   \
        unsigned db = smem_u32(sbuf + PLANE + s0 * 16);                           \
        cp16(da + r0 * ROWB, ga);                                                 \
        cp16(da + r1 * ROWB, ga + (size_t)64 * DMODEL);                           \
        cp16(db + r0 * ROWB, gb);                                                 \
        cp16(db + r1 * ROWB, gb + (size_t)64 * DMODEL);                           \
        asm volatile("cp.async.commit_group;" ::: "memory");                      \
    }

    ISSUE(0); ISSUE(1); ISSUE(2);

    const int a_row = wm * 64 + (lane & 15);
    const unsigned a_coff = (lane >> 4) * 16;
    const int b_row = wn * 32 + (lane & 7) + ((lane >> 4) << 3);
    const unsigned b_coff = ((lane >> 3) & 1) * 16;

    // prologue: stages 0 and 1 arrived, then load frags(chunk0, ks0)
    asm volatile("cp.async.wait_group 1;" ::: "memory");
    __syncthreads();

    Frags f0, f1;
    {
        const unsigned sA = smem_u32(smem);
        load_frags(f0, sA, sA + PLANE, 0, a_row, a_coff, b_row, b_coff);
    }

    for (int c = 0; c < NCHUNK; c++) {
        // invariant at top: stages c and c+1 visible to all threads; f0 = (c, ks0)
        if (c + 3 < NCHUNK) ISSUE(c + 3);   // writes buffer (c+3)%4 == (c-1)%4, freed by last barrier

        const unsigned sA = smem_u32(smem + (c & (NSTAGE - 1)) * STAGE);
        const unsigned sB = sA + PLANE;

        load_frags(f1, sA, sB, 32, a_row, a_coff, b_row, b_coff);   // (c, ks1)
        do_mma(acc, f0);                                            // (c, ks0)

        if (c + 1 < NCHUNK) {
            const unsigned nA = smem_u32(smem + ((c + 1) & (NSTAGE - 1)) * STAGE);
            load_frags(f0, nA, nA + PLANE, 0, a_row, a_coff, b_row, b_coff); // (c+1, ks0)
        }
        do_mma(acc, f1);                                            // (c, ks1)

        if (c + 1 < NCHUNK) {
            // need stage c+2 arrived before next barrier (for next iteration's prefetch)
            if (c + 3 < NCHUNK) {
                asm volatile("cp.async.wait_group 1;" ::: "memory");
            } else {
                asm volatile("cp.async.wait_group 0;" ::: "memory");
            }
            __syncthreads();
        }
    }
#undef ISSUE

    // ---- epilogue ----
    const int er = lane >> 2, ec = (lane & 3) * 2;
#pragma unroll
    for (int mt = 0; mt < 4; mt++) {
        const int row = bm + wm * 64 + mt * 16 + er;
#pragma unroll
        for (int nt = 0; nt < 4; nt++) {
            const int col = bn + wn * 32 + nt * 8 + ec;
            const float b0 = bias[col], b1 = bias[col + 1];
            float v0 = acc[mt][nt][0] + b0, v1 = acc[mt][nt][1] + b1;
            float v2 = acc[mt][nt][2] + b0, v3 = acc[mt][nt][3] + b1;
            if (mode == 0) {
                *(float2*)&C[(size_t)row * DMODEL + col] = make_float2(v0, v1);
                *(float2*)&C[(size_t)(row + 8) * DMODEL + col] = make_float2(v2, v3);
            } else {
                *(unsigned*)&Ch[(size_t)row * DMODEL + col] = packf16(v0, v1);
                *(unsigned*)&Ch[(size_t)(row + 8) * DMODEL + col] = packf16(v2, v3);
            }
        }
    }
}

// ---- fused QKV projection: grid (24, 32); blockIdx.x/8 selects Q/K/V ----
__global__ __launch_bounds__(256, 2)
void gemm_qkv(const float* __restrict__ bq, const float* __restrict__ bk,
              const float* __restrict__ bv)
{
    extern __shared__ char smem[];
    const int which = blockIdx.x >> 3;
    const int bn = (blockIdx.x & 7) * 128;
    const int bm = blockIdx.y * 128;
    const unsigned short* B = (which == 0) ? g_Wq16 : (which == 1) ? g_Wk16 : g_Wv16;
    const float* bias = (which == 0) ? bq : (which == 1) ? bk : bv;
    unsigned short* Ch = (which == 0) ? g_q16 : (which == 1) ? g_k16 : g_v16;
    gemm_body(smem, g_x16, B, bias, bm, bn, 1, nullptr, Ch);
}

// ---- output projection: ctx(f16) @ Wo^T + bo -> fp32 out ----
__global__ __launch_bounds__(256, 2)
void gemm_out(const float* __restrict__ bo, float* __restrict__ out)
{
    extern __shared__ char smem[];
    gemm_body(smem, g_c16, g_Wo16, bo,
              blockIdx.y * 128, blockIdx.x * 128, 0, out, nullptr);
}

// ---------------- tensorized sliding-window attention (fp16) ----------------
// grid (S/128, H), 256 threads (8 warps). Warp w: 16 query rows (local 16w..16w+15),
// keys local [16w, 16w+143] of a shared 256-row K/V tile (9 pr-tiles of 16).
#define AT_Q   128
#define AT_KW  256
#define AROWB  144
#define A_SQ   0
#define A_SK   (AT_Q * AROWB)               // 18432
#define A_SV   (A_SK + AT_KW * AROWB)       // 55296
#define A_SMEM (A_SV + AT_KW * AROWB)       // 92160 -> 2 CTAs/SM

__global__ __launch_bounds__(256, 2)
void attn_mma()
{
    extern __shared__ char smem[];
    const unsigned sb = smem_u32(smem);
    const int t = threadIdx.x, lane = t & 31, w = t >> 5;
    const int h = blockIdx.y;
    const int q0 = blockIdx.x * AT_Q;
    const int j0 = q0 - 64;
    const int col = h * HEAD_DIM;

    // ---- load Q (128x64) ----
#pragma unroll
    for (int i = 0; i < 4; i++) {
        int idx = t + i * 256;               // 0..1023
        int r = idx >> 3, sg = idx & 7;
        *(uint4*)(smem + A_SQ + r * AROWB + sg * 16) =
            *(const uint4*)(g_q16 + (size_t)(q0 + r) * DMODEL + col + sg * 8);
    }
    // ---- load K,V window (256x64), zero-fill out of range ----
#pragma unroll
    for (int i = 0; i < 8; i++) {
        int idx = t + i * 256;               // 0..2047
        int r = idx >> 3, sg = idx & 7;
        int j = j0 + r;
        uint4 kv = make_uint4(0,0,0,0), vv = kv;
        if ((unsigned)j < (unsigned)S_LEN) {
            size_t go = (size_t)j * DMODEL + col + sg * 8;
            kv = *(const uint4*)(g_k16 + go);
            vv = *(const uint4*)(g_v16 + go);
        }
        unsigned so = r * AROWB + sg * 16;
        *(uint4*)(smem + A_SK + so) = kv;
        *(uint4*)(smem + A_SV + so) = vv;
    }
    __syncthreads();

    // ---- S = Q K^T over warp's 144-key window ----
    float sc[18][4];
#pragma unroll
    for (int nt = 0; nt < 18; nt++)
#pragma unroll
        for (int r = 0; r < 4; r++) sc[nt][r] = 0.f;

    const int lk0 = w * 16;
    const unsigned a_base = (unsigned)((w * 16 + (lane & 15)) * AROWB) + ((lane >> 4) << 4);
    const int b_lrow = (lane & 7) + ((lane >> 4) << 3);
    const unsigned b_coff = ((lane >> 3) & 1) << 4;

#pragma unroll
    for (int kc = 0; kc < 4; kc++) {
        unsigned afr[4];
        ldm_x4(afr, sb + A_SQ + a_base + kc * 32);
#pragma unroll
        for (int pr = 0; pr < 9; pr++) {
            unsigned bfr[4];
            ldm_x4(bfr, sb + A_SK + (unsigned)((lk0 + pr * 16 + b_lrow) * AROWB) + kc * 32 + b_coff);
            mma_f16(sc[pr * 2],     afr, &bfr[0]);
            mma_f16(sc[pr * 2 + 1], afr, &bfr[2]);
        }
    }

    // ---- mask + softmax ----
    const int er = lane >> 2, ec = (lane & 3) * 2;
    const float SC = 0.125f * 1.44269504088896f;
    float m0 = -1e30f, m1 = -1e30f;
#pragma unroll
    for (int nt = 0; nt < 18; nt++) {
        const int d = nt * 8 + ec;
        const int j = j0 + lk0 + d;
        bool v00 = ((unsigned)(d     - er)     <= 128u) && ((unsigned)j       < (unsigned)S_LEN);
        bool v01 = ((unsigned)(d + 1 - er)     <= 128u) && ((unsigned)(j + 1) < (unsigned)S_LEN);
        bool v10 = ((unsigned)(d     - er - 8) <= 128u) && ((unsigned)j       < (unsigned)S_LEN);
        bool v11 = ((unsigned)(d + 1 - er - 8) <= 128u) && ((unsigned)(j + 1) < (unsigned)S_LEN);
        sc[nt][0] = v00 ? sc[nt][0] * SC : -1e30f;
        sc[nt][1] = v01 ? sc[nt][1] * SC : -1e30f;
        sc[nt][2] = v10 ? sc[nt][2] * SC : -1e30f;
        sc[nt][3] = v11 ? sc[nt][3] * SC : -1e30f;
        m0 = fmaxf(m0, fmaxf(sc[nt][0], sc[nt][1]));
        m1 = fmaxf(m1, fmaxf(sc[nt][2], sc[nt][3]));
    }
    m0 = fmaxf(m0, __shfl_xor_sync(0xffffffffu, m0, 1));
    m0 = fmaxf(m0, __shfl_xor_sync(0xffffffffu, m0, 2));
    m1 = fmaxf(m1, __shfl_xor_sync(0xffffffffu, m1, 1));
    m1 = fmaxf(m1, __shfl_xor_sync(0xffffffffu, m1, 2));

    float s0 = 0.f, s1 = 0.f;
#pragma unroll
    for (int nt = 0; nt < 18; nt++) {
        sc[nt][0] = ex2(sc[nt][0] - m0);
        sc[nt][1] = ex2(sc[nt][1] - m0);
        sc[nt][2] = ex2(sc[nt][2] - m1);
        sc[nt][3] = ex2(sc[nt][3] - m1);
        s0 += sc[nt][0] + sc[nt][1];
        s1 += sc[nt][2] + sc[nt][3];
    }
    s0 += __shfl_xor_sync(0xffffffffu, s0, 1);
    s0 += __shfl_xor_sync(0xffffffffu, s0, 2);
    s1 += __shfl_xor_sync(0xffffffffu, s1, 1);
    s1 += __shfl_xor_sync(0xffffffffu, s1, 2);
    const float inv0 = rcp(s0), inv1 = rcp(s1);

    // ---- O = P V over the same 144-key window ----
    float oa[8][4];
#pragma unroll
    for (int nt = 0; nt < 8; nt++)
#pragma unroll
        for (int r = 0; r < 4; r++) oa[nt][r] = 0.f;

#pragma unroll
    for (int kc = 0; kc < 9; kc++) {
        unsigned ph[4];
        ph[0] = packf16(sc[2 * kc][0],     sc[2 * kc][1]);
        ph[1] = packf16(sc[2 * kc][2],     sc[2 * kc][3]);
        ph[2] = packf16(sc[2 * kc + 1][0], sc[2 * kc + 1][1]);
        ph[3] = packf16(sc[2 * kc + 1][2], sc[2 * kc + 1][3]);
#pragma unroll
        for (int dt = 0; dt < 4; dt++) {
            unsigned vh[4];
            unsigned voff = (unsigned)((lk0 + kc * 16 + (lane & 15)) * AROWB) + dt * 32 + ((lane >> 4) << 4);
            ldm_x4t(vh, sb + A_SV + voff);
            mma_f16(oa[2 * dt],     ph, &vh[0]);
            mma_f16(oa[2 * dt + 1], ph, &vh[2]);
        }
    }

    // ---- normalize + write ctx as fp16 ----
    const int row0 = q0 + w * 16 + er;
#pragma unroll
    for (int nt = 0; nt < 8; nt++) {
        const int oc = col + nt * 8 + ec;
        float v0 = oa[nt][0] * inv0, v1 = oa[nt][1] * inv0;
        float v2 = oa[nt][2] * inv1, v3 = oa[nt][3] * inv1;
        *(unsigned*)&g_c16[(size_t)row0 * DMODEL + oc] = packf16(v0, v1);
        *(unsigned*)&g_c16[(size_t)(row0 + 8) * DMODEL + oc] = packf16(v2, v3);
    }
}

// ---------------- launch ----------------
extern "C" void kernel_launch(void* const* d_in, const int* in_sizes, int n_in,
                              void* d_out, int out_size)
{
    const float* x  = (const float*)d_in[0];
    const float* Wq = (const float*)d_in[1];
    const float* bq = (const float*)d_in[2];
    const float* Wk = (const float*)d_in[3];
    const float* bk = (const float*)d_in[4];
    const float* Wv = (const float*)d_in[5];
    const float* bv = (const float*)d_in[6];
    const float* Wo = (const float*)d_in[7];
    const float* bo = (const float*)d_in[8];
    float* out = (float*)d_out;

    cudaFuncSetAttribute(gemm_qkv, cudaFuncAttributeMaxDynamicSharedMemorySize, GSMEM);
    cudaFuncSetAttribute(gemm_out, cudaFuncAttributeMaxDynamicSharedMemorySize, GSMEM);
    cudaFuncSetAttribute(attn_mma, cudaFuncAttributeMaxDynamicSharedMemorySize, A_SMEM);

    to_f16_all<<<8192, 256>>>(x, Wq, Wk, Wv, Wo);

    dim3 gq(24, 32);                       // fused Q,K,V
    gemm_qkv<<<gq, 256, GSMEM>>>(bq, bk, bv);

    dim3 ga(S_LEN / AT_Q, N_HEADS);        // (32, 16)
    attn_mma<<<ga, 256, A_SMEM>>>();

    dim3 go(8, 32);
    gemm_out<<<go, 256, GSMEM>>>(bo, out);
}